// round 11
// baseline (speedup 1.0000x reference)
#include <cuda_runtime.h>
#include <cstdint>
#include <cstddef>

#define BT 256
#define TT 250
#define II 700
#define HH 128
#define OO 20

// Scratch: xin[b][t][h] = (x @ w_ih1 + b_ih1)
__device__ float g_xin[BT * TT * HH];
// layer-2 spike bit-words: [b][t][4] (bit j of word w = spike of h = w*32+j)
__device__ unsigned int g_spk[BT * TT * 4];

// Correctly-rounded f32 exp (matches glibc scalar expf used by XLA:CPU).
__device__ __forceinline__ float exp_cr(float x) {
    return (float)exp((double)x);
}

// packed f32x2 helpers
__device__ __forceinline__ unsigned long long pack2(float lo, float hi) {
    unsigned long long r;
    asm("mov.b64 %0, {%1, %2};" : "=l"(r) : "f"(lo), "f"(hi));
    return r;
}
__device__ __forceinline__ void unpack2(unsigned long long v, float& lo, float& hi) {
    asm("mov.b64 {%0, %1}, %2;" : "=f"(lo), "=f"(hi) : "l"(v));
}
__device__ __forceinline__ void ffma2(unsigned long long& d, unsigned long long a,
                                      unsigned long long b) {
    asm("fma.rn.f32x2 %0, %1, %2, %0;" : "+l"(d) : "l"(a), "l"(b));
}

// ---------------------------------------------------------------------------
// Kernel 1: xin = x @ w_ih1 + b_ih1 — FULL FP32, single ascending-k FMA chain
// per output (numerics identical to R8-R10). Register-staged pipeline.
// ---------------------------------------------------------------------------
__global__ __launch_bounds__(256) void gemm_xin_kernel(
    const float* __restrict__ x, const float* __restrict__ w,
    const float* __restrict__ bias)
{
    __shared__ float a_sm[16][132];
    __shared__ float b_sm[16][128];

    const int tid = threadIdx.x;
    const int m0 = blockIdx.x * 128;
    const int tx = tid & 15, ty = tid >> 4;
    const int r0 = ty * 8;

    const int a_ml = tid >> 4, a_kl = tid & 15;
    const int b_kl = tid >> 7, b_hh = tid & 127;

    unsigned long long acc[8][4];
#pragma unroll
    for (int r = 0; r < 8; r++)
#pragma unroll
        for (int j = 0; j < 4; j++) acc[r][j] = 0ull;

    const int NT = (II + 15) / 16;
    float ra[8], rb[8];

    {
        int k0 = 0;
#pragma unroll
        for (int p = 0; p < 8; p++) {
            int k = k0 + a_kl;
            ra[p] = (k < II) ? x[(size_t)(m0 + a_ml + p * 16) * II + k] : 0.f;
        }
#pragma unroll
        for (int p = 0; p < 8; p++) {
            int k = k0 + b_kl + p * 2;
            rb[p] = (k < II) ? w[k * HH + b_hh] : 0.f;
        }
    }

    for (int kt = 0; kt < NT; kt++) {
#pragma unroll
        for (int p = 0; p < 8; p++) a_sm[a_kl][a_ml + p * 16] = ra[p];
#pragma unroll
        for (int p = 0; p < 8; p++) b_sm[b_kl + p * 2][b_hh] = rb[p];
        __syncthreads();

        if (kt + 1 < NT) {
            int k0 = (kt + 1) * 16;
#pragma unroll
            for (int p = 0; p < 8; p++) {
                int k = k0 + a_kl;
                ra[p] = (k < II) ? x[(size_t)(m0 + a_ml + p * 16) * II + k] : 0.f;
            }
#pragma unroll
            for (int p = 0; p < 8; p++) {
                int k = k0 + b_kl + p * 2;
                rb[p] = (k < II) ? w[k * HH + b_hh] : 0.f;
            }
        }

#pragma unroll
        for (int kk = 0; kk < 16; kk++) {
            float a[8];
            unsigned long long bb[4];
#pragma unroll
            for (int r = 0; r < 8; r++) a[r] = a_sm[kk][r0 + r];
            const float2* bp = reinterpret_cast<const float2*>(&b_sm[kk][2 * tx]);
#pragma unroll
            for (int j = 0; j < 4; j++) { float2 v = bp[16 * j]; bb[j] = pack2(v.x, v.y); }
#pragma unroll
            for (int r = 0; r < 8; r++) {
                unsigned long long ad = pack2(a[r], a[r]);
#pragma unroll
                for (int j = 0; j < 4; j++) ffma2(acc[r][j], ad, bb[j]);
            }
        }
        __syncthreads();
    }

#pragma unroll
    for (int r = 0; r < 8; r++) {
        int m = m0 + r0 + r;
#pragma unroll
        for (int j = 0; j < 4; j++) {
            float lo, hi;
            unpack2(acc[r][j], lo, hi);
            int c = 2 * tx + 32 * j;
            float2 v;
            v.x = __fadd_rn(lo, bias[c]);
            v.y = __fadd_rn(hi, bias[c + 1]);
            *reinterpret_cast<float2*>(&g_xin[(size_t)m * HH + c]) = v;
        }
    }
}

// ---------------------------------------------------------------------------
// Kernel 2: the 250-step scan. 128 blocks x 256 thr, 1 batch row per thread.
// Sparse dots with MANUALLY INTERLEAVED chains: each outer iteration retires
// one bit from every active word-chain (8 for layer1, 4 for layer2), so the
// independent LDS->FADD chains overlap instead of serializing. Per-chain add
// order unchanged vs R10 -> bit-identical output.
// ---------------------------------------------------------------------------
#define SCAN_SMEM_FLOATS (3 * 16384 + 3 * 128 + 16)

__global__ __launch_bounds__(256) void scan_kernel(
    const float* __restrict__ mask,
    const float* __restrict__ w_h1h1, const float* __restrict__ b_h1h1,
    const float* __restrict__ w_h1h2, const float* __restrict__ b_h1h2,
    const float* __restrict__ w_h2h2, const float* __restrict__ b_h2h2,
    const float* __restrict__ tau_adp_h1, const float* __restrict__ tau_adp_h2,
    const float* __restrict__ tau_m_h1,   const float* __restrict__ tau_m_h2,
    const float* __restrict__ hid1_mem0, const float* __restrict__ hid2_mem0,
    float* __restrict__ out)
{
    extern __shared__ float sm[];
    float*  w11  = sm;                  // [k][h] masked, fp32
    float*  w12  = w11 + 16384;         // [k][h] fp32
    float*  w22  = w12 + 16384;         // [k][h] masked, fp32
    float*  b11s = w22 + 16384;
    float*  b12s = b11s + 128;
    float*  b22s = b12s + 128;
    unsigned int* s1w = (unsigned int*)(b22s + 128);  // [2 rows][4 words]
    unsigned int* s2w = s1w + 8;                      // [2 rows][4 words]

    const int tid = threadIdx.x;
    const int h   = tid & 127;
    const int r   = tid >> 7;
    const int wi  = tid >> 5;
    const int l   = tid & 31;
    const int b   = blockIdx.x * 2 + r;

#pragma unroll 4
    for (int p = 0; p < 64; p++) {
        int i = p * 256 + tid;
        w11[i] = __fmul_rn(w_h1h1[i], mask[i]);
        w12[i] = w_h1h2[i];
        w22[i] = __fmul_rn(w_h2h2[i], mask[16384 + i]);
    }
    if (r == 0) {
        b11s[h] = b_h1h1[h];
        b12s[h] = b_h1h2[h];
        b22s[h] = b_h2h2[h];
    }
    if (tid < 16) s1w[tid] = 0u;

    const float a1 = exp_cr(__fdiv_rn(-1.0f, tau_m_h1[h]));
    const float r1 = exp_cr(__fdiv_rn(-1.0f, tau_adp_h1[h]));
    const float a2 = exp_cr(__fdiv_rn(-1.0f, tau_m_h2[h]));
    const float r2 = exp_cr(__fdiv_rn(-1.0f, tau_adp_h2[h]));
    const float oma1 = __fsub_rn(1.f, a1);
    const float omr1 = __fsub_rn(1.f, r1);
    const float oma2 = __fsub_rn(1.f, a2);
    const float omr2 = __fsub_rn(1.f, r2);

    float h1m = hid1_mem0[(size_t)b * 128 + h];
    float h2m = hid2_mem0[(size_t)b * 128 + h];
    float h1sp = 0.f, h2sp = 0.f;
    float bb1 = 0.01f, bb2 = 0.01f;
    float cnt1 = 0.f, cnt2 = 0.f;

    unsigned int u1[4] = {0u, 0u, 0u, 0u};
    unsigned int u2[4] = {0u, 0u, 0u, 0u};

    __syncthreads();

    const float* xin = g_xin + (size_t)b * TT * HH + h;
    float xa = xin[0];

    for (int t = 0; t < TT; t++) {
        float xan = (t + 1 < TT) ? xin[(size_t)(t + 1) * HH] : 0.f;

        // --- layer-1 recurrent + layer-2 self dots: 8 interleaved chains ---
        float p1[4], p2[4];
        unsigned int d1[4], d2[4];
#pragma unroll
        for (int w = 0; w < 4; w++) {
            p1[w] = 0.f; p2[w] = 0.f; d1[w] = u1[w]; d2[w] = u2[w];
        }
        bool go = true;
        while (go) {
            go = false;
#pragma unroll
            for (int w = 0; w < 4; w++) {
                unsigned int dd = d1[w];
                if (dd) {
                    int j = __ffs(dd) - 1;
                    d1[w] = dd & (dd - 1);
                    p1[w] = __fadd_rn(p1[w], w11[(w << 12) + (j << 7) + h]);
                    go = true;
                }
                dd = d2[w];
                if (dd) {
                    int j = __ffs(dd) - 1;
                    d2[w] = dd & (dd - 1);
                    p2[w] = __fadd_rn(p2[w], w22[(w << 12) + (j << 7) + h]);
                    go = true;
                }
            }
        }
        float m1  = __fadd_rn(__fadd_rn(__fadd_rn(p1[0], p1[1]), p1[2]), p1[3]);
        float m22 = __fadd_rn(__fadd_rn(__fadd_rn(p2[0], p2[1]), p2[2]), p2[3]);

        // --- layer 1 update (R8 elementwise numerics) ---
        float i1 = __fadd_rn(__fadd_rn(xa, m1), b11s[h]);
        bb1 = __fadd_rn(__fmul_rn(r1, bb1), __fmul_rn(omr1, h1sp));
        float B1 = __fadd_rn(0.01f, __fmul_rn(1.8f, bb1));
        h1m = __fsub_rn(__fadd_rn(__fmul_rn(h1m, a1), __fmul_rn(oma1, i1)),
                        __fmul_rn(B1, h1sp));
        float s1n = (__fsub_rn(h1m, B1) > 0.f) ? 1.f : 0.f;
        cnt1 += s1n; h1sp = s1n;

        unsigned int wd1 = __ballot_sync(0xffffffffu, s1n != 0.f);
        if (l == 0) s1w[wi] = wd1;
        __syncthreads();

        unsigned int n1[4];
#pragma unroll
        for (int w = 0; w < 4; w++) n1[w] = s1w[(r << 2) + w];

        // --- layer 2 forward dot: 4 interleaved chains over NEW s1 ---
        float q[4];
        unsigned int e1[4];
#pragma unroll
        for (int w = 0; w < 4; w++) { q[w] = 0.f; e1[w] = n1[w]; }
        go = true;
        while (go) {
            go = false;
#pragma unroll
            for (int w = 0; w < 4; w++) {
                unsigned int dd = e1[w];
                if (dd) {
                    int j = __ffs(dd) - 1;
                    e1[w] = dd & (dd - 1);
                    q[w] = __fadd_rn(q[w], w12[(w << 12) + (j << 7) + h]);
                    go = true;
                }
            }
        }
        float m12 = __fadd_rn(__fadd_rn(__fadd_rn(q[0], q[1]), q[2]), q[3]);

        float i2 = __fadd_rn(__fadd_rn(__fadd_rn(m12, b12s[h]), m22), b22s[h]);
        bb2 = __fadd_rn(__fmul_rn(r2, bb2), __fmul_rn(omr2, h2sp));
        float B2 = __fadd_rn(0.01f, __fmul_rn(1.8f, bb2));
        h2m = __fsub_rn(__fadd_rn(__fmul_rn(h2m, a2), __fmul_rn(oma2, i2)),
                        __fmul_rn(B2, h2sp));
        float s2n = (__fsub_rn(h2m, B2) > 0.f) ? 1.f : 0.f;
        cnt2 += s2n; h2sp = s2n;

        unsigned int wd2 = __ballot_sync(0xffffffffu, s2n != 0.f);
        if (l == 0) {
            s2w[wi] = wd2;
            g_spk[((size_t)b * TT + t) * 4 + (wi & 3)] = wd2;
        }
        __syncthreads();

#pragma unroll
        for (int w = 0; w < 4; w++) {
            u1[w] = n1[w];
            u2[w] = s2w[(r << 2) + w];
        }
        xa = xan;
    }

    const float T250 = 250.0f;
    out[5120 + (size_t)b * 128 + h]         = cnt1 / T250;
    out[5120 + 32768 + (size_t)b * 128 + h] = cnt2 / T250;
}

// ---------------------------------------------------------------------------
// Kernel 3: readout — unchanged from R9/R10 (passed).
// ---------------------------------------------------------------------------
__global__ __launch_bounds__(128) void readout_kernel(
    const float* __restrict__ w_h2o, const float* __restrict__ b_h2o,
    const float* __restrict__ tau_m_o, const float* __restrict__ out_mem0,
    float* __restrict__ out)
{
    __shared__ float w2o_sm[128 * 20];
    __shared__ unsigned int spk[TT][4];
    __shared__ float io_sm[TT][20];

    const int b = blockIdx.x;
    const int tid = threadIdx.x;

    for (int i = tid; i < 128 * 20; i += 128) w2o_sm[i] = w_h2o[i];
    for (int i = tid; i < TT * 4; i += 128)
        ((unsigned int*)spk)[i] = g_spk[(size_t)b * TT * 4 + i];
    __syncthreads();

    for (int p = tid; p < TT * 20; p += 128) {
        int t = p / 20;
        int o = p - t * 20;
        float acc = 0.f;
#pragma unroll
        for (int w = 0; w < 4; w++) {
            unsigned int word = spk[t][w];
            while (word) {
                int j = __ffs(word) - 1; word &= word - 1;
                acc = __fadd_rn(acc, w2o_sm[(w * 32 + j) * 20 + o]);
            }
        }
        io_sm[t][o] = acc;
    }
    __syncthreads();

    if (tid < 32) {
        const int ll = tid;
        float om = 0.f, ao = 0.f, bo = 0.f, accm = 0.f;
        if (ll < 20) {
            om = out_mem0[(size_t)b * 20 + ll];
            ao = (float)exp((double)__fdiv_rn(-1.0f, tau_m_o[ll]));
            bo = b_h2o[ll];
        }
        const float omao = __fsub_rn(1.f, ao);
        for (int t = 0; t < TT; t++) {
            float iov = (ll < 20) ? __fadd_rn(io_sm[t][ll], bo) : 0.f;
            om = __fadd_rn(__fmul_rn(om, ao), __fmul_rn(omao, iov));
            if (t > 10) {
                float v = (ll < 20) ? om : -3.402823466e38f;
#pragma unroll
                for (int d = 16; d > 0; d >>= 1)
                    v = fmaxf(v, __shfl_xor_sync(0xffffffffu, v, d));
                float e = (ll < 20) ? (float)exp((double)__fsub_rn(om, v)) : 0.f;
                float ssum = 0.f;
#pragma unroll
                for (int o = 0; o < 20; o++)
                    ssum = __fadd_rn(ssum, __shfl_sync(0xffffffffu, e, o));
                if (ll < 20) accm = __fadd_rn(accm, __fdiv_rn(e, ssum));
            }
        }
        if (ll < 20) out[(size_t)b * 20 + ll] = accm;
    }
}

// ---------------------------------------------------------------------------
// Kernel 4: A_norm — unchanged (passed). Launched FIRST so the fixed
// "-s 5 -c 1" ncu window lands on a heavy kernel next round.
// ---------------------------------------------------------------------------
__global__ __launch_bounds__(256) void anorm_kernel(
    const float* __restrict__ w_h1h1, const float* __restrict__ w_h2h2,
    const float* __restrict__ mask, float* __restrict__ out)
{
    __shared__ float red1[256];
    __shared__ float red2[256];
    int tid = threadIdx.x;
    float s1 = 0.f, s2 = 0.f;
    for (int i = tid; i < 16384; i += 256) {
        s1 = __fadd_rn(s1, fabsf(__fmul_rn(w_h1h1[i], mask[i])));
        s2 = __fadd_rn(s2, fabsf(__fmul_rn(w_h2h2[i], mask[16384 + i])));
    }
    red1[tid] = s1;
    red2[tid] = s2;
    __syncthreads();
#pragma unroll
    for (int st = 128; st > 0; st >>= 1) {
        if (tid < st) {
            red1[tid] = __fadd_rn(red1[tid], red1[tid + st]);
            red2[tid] = __fadd_rn(red2[tid], red2[tid + st]);
        }
        __syncthreads();
    }
    if (tid == 0) out[5120 + 2 * 32768] = __fadd_rn(red1[0], red2[0]);
}

// ---------------------------------------------------------------------------
extern "C" void kernel_launch(void* const* d_in, const int* in_sizes, int n_in,
                              void* d_out, int out_size)
{
    (void)in_sizes; (void)n_in; (void)out_size;
    const float* x          = (const float*)d_in[0];
    const float* mask       = (const float*)d_in[1];
    const float* w_ih1      = (const float*)d_in[2];
    const float* b_ih1      = (const float*)d_in[3];
    const float* w_h1h1     = (const float*)d_in[4];
    const float* b_h1h1     = (const float*)d_in[5];
    const float* w_h1h2     = (const float*)d_in[6];
    const float* b_h1h2     = (const float*)d_in[7];
    const float* w_h2h2     = (const float*)d_in[8];
    const float* b_h2h2     = (const float*)d_in[9];
    const float* w_h2o      = (const float*)d_in[10];
    const float* b_h2o      = (const float*)d_in[11];
    const float* tau_adp_h1 = (const float*)d_in[12];
    const float* tau_adp_h2 = (const float*)d_in[13];
    const float* tau_m_h1   = (const float*)d_in[14];
    const float* tau_m_h2   = (const float*)d_in[15];
    const float* tau_m_o    = (const float*)d_in[16];
    const float* hid1_mem0  = (const float*)d_in[17];
    const float* hid2_mem0  = (const float*)d_in[18];
    const float* out_mem0   = (const float*)d_in[19];
    float* out = (float*)d_out;

    // anorm first (independent) — shifts the fixed ncu capture window onto
    // the GEMM for the next profiling round.
    anorm_kernel<<<1, 256>>>(w_h1h1, w_h2h2, mask, out);

    gemm_xin_kernel<<<(BT * TT) / 128, 256>>>(x, w_ih1, b_ih1);

    const int smem_bytes = SCAN_SMEM_FLOATS * (int)sizeof(float);
    cudaFuncSetAttribute(scan_kernel, cudaFuncAttributeMaxDynamicSharedMemorySize,
                         smem_bytes);
    scan_kernel<<<BT / 2, 256, smem_bytes>>>(
        mask, w_h1h1, b_h1h1, w_h1h2, b_h1h2, w_h2h2, b_h2h2,
        tau_adp_h1, tau_adp_h2, tau_m_h1, tau_m_h2,
        hid1_mem0, hid2_mem0, out);

    readout_kernel<<<BT, 128>>>(w_h2o, b_h2o, tau_m_o, out_mem0, out);
}

// round 12
// speedup vs baseline: 1.3902x; 1.3902x over previous
#include <cuda_runtime.h>
#include <cstdint>
#include <cstddef>

#define BT 256
#define TT 250
#define II 700
#define HH 128
#define OO 20

// Scratch: xin[b][t][h] = (x @ w_ih1 + b_ih1)
__device__ float g_xin[BT * TT * HH];
// layer-2 spike bit-words: [b][t][4] (bit j of word w = spike of h = w*32+j)
__device__ unsigned int g_spk[BT * TT * 4];

// Correctly-rounded f32 exp (matches glibc scalar expf used by XLA:CPU).
__device__ __forceinline__ float exp_cr(float x) {
    return (float)exp((double)x);
}

// packed f32x2 helpers
__device__ __forceinline__ unsigned long long pack2(float lo, float hi) {
    unsigned long long r;
    asm("mov.b64 %0, {%1, %2};" : "=l"(r) : "f"(lo), "f"(hi));
    return r;
}
__device__ __forceinline__ void unpack2(unsigned long long v, float& lo, float& hi) {
    asm("mov.b64 {%0, %1}, %2;" : "=f"(lo), "=f"(hi) : "l"(v));
}
__device__ __forceinline__ void ffma2(unsigned long long& d, unsigned long long a,
                                      unsigned long long b) {
    asm("fma.rn.f32x2 %0, %1, %2, %0;" : "+l"(d) : "l"(a), "l"(b));
}

// ---------------------------------------------------------------------------
// Kernel 1: xin = x @ w_ih1 + b_ih1 — FULL FP32, single ascending-k FMA chain
// per output (numerics identical to R8-R10). Register-staged pipeline.
// ---------------------------------------------------------------------------
__global__ __launch_bounds__(256) void gemm_xin_kernel(
    const float* __restrict__ x, const float* __restrict__ w,
    const float* __restrict__ bias)
{
    __shared__ float a_sm[16][132];
    __shared__ float b_sm[16][128];

    const int tid = threadIdx.x;
    const int m0 = blockIdx.x * 128;
    const int tx = tid & 15, ty = tid >> 4;
    const int r0 = ty * 8;

    const int a_ml = tid >> 4, a_kl = tid & 15;
    const int b_kl = tid >> 7, b_hh = tid & 127;

    unsigned long long acc[8][4];
#pragma unroll
    for (int r = 0; r < 8; r++)
#pragma unroll
        for (int j = 0; j < 4; j++) acc[r][j] = 0ull;

    const int NT = (II + 15) / 16;
    float ra[8], rb[8];

    {
        int k0 = 0;
#pragma unroll
        for (int p = 0; p < 8; p++) {
            int k = k0 + a_kl;
            ra[p] = (k < II) ? x[(size_t)(m0 + a_ml + p * 16) * II + k] : 0.f;
        }
#pragma unroll
        for (int p = 0; p < 8; p++) {
            int k = k0 + b_kl + p * 2;
            rb[p] = (k < II) ? w[k * HH + b_hh] : 0.f;
        }
    }

    for (int kt = 0; kt < NT; kt++) {
#pragma unroll
        for (int p = 0; p < 8; p++) a_sm[a_kl][a_ml + p * 16] = ra[p];
#pragma unroll
        for (int p = 0; p < 8; p++) b_sm[b_kl + p * 2][b_hh] = rb[p];
        __syncthreads();

        if (kt + 1 < NT) {
            int k0 = (kt + 1) * 16;
#pragma unroll
            for (int p = 0; p < 8; p++) {
                int k = k0 + a_kl;
                ra[p] = (k < II) ? x[(size_t)(m0 + a_ml + p * 16) * II + k] : 0.f;
            }
#pragma unroll
            for (int p = 0; p < 8; p++) {
                int k = k0 + b_kl + p * 2;
                rb[p] = (k < II) ? w[k * HH + b_hh] : 0.f;
            }
        }

#pragma unroll
        for (int kk = 0; kk < 16; kk++) {
            float a[8];
            unsigned long long bb[4];
#pragma unroll
            for (int r = 0; r < 8; r++) a[r] = a_sm[kk][r0 + r];
            const float2* bp = reinterpret_cast<const float2*>(&b_sm[kk][2 * tx]);
#pragma unroll
            for (int j = 0; j < 4; j++) { float2 v = bp[16 * j]; bb[j] = pack2(v.x, v.y); }
#pragma unroll
            for (int r = 0; r < 8; r++) {
                unsigned long long ad = pack2(a[r], a[r]);
#pragma unroll
                for (int j = 0; j < 4; j++) ffma2(acc[r][j], ad, bb[j]);
            }
        }
        __syncthreads();
    }

#pragma unroll
    for (int r = 0; r < 8; r++) {
        int m = m0 + r0 + r;
#pragma unroll
        for (int j = 0; j < 4; j++) {
            float lo, hi;
            unpack2(acc[r][j], lo, hi);
            int c = 2 * tx + 32 * j;
            float2 v;
            v.x = __fadd_rn(lo, bias[c]);
            v.y = __fadd_rn(hi, bias[c + 1]);
            *reinterpret_cast<float2*>(&g_xin[(size_t)m * HH + c]) = v;
        }
    }
}

// ---------------------------------------------------------------------------
// Kernel 2: the 250-step scan — EXACT R10 form (best measured: 867 total).
// 128 blocks x 256 thr, 1 batch row per thread, sparse per-word chains.
// ---------------------------------------------------------------------------
#define SCAN_SMEM_FLOATS (3 * 16384 + 3 * 128 + 16)

__global__ __launch_bounds__(256) void scan_kernel(
    const float* __restrict__ mask,
    const float* __restrict__ w_h1h1, const float* __restrict__ b_h1h1,
    const float* __restrict__ w_h1h2, const float* __restrict__ b_h1h2,
    const float* __restrict__ w_h2h2, const float* __restrict__ b_h2h2,
    const float* __restrict__ tau_adp_h1, const float* __restrict__ tau_adp_h2,
    const float* __restrict__ tau_m_h1,   const float* __restrict__ tau_m_h2,
    const float* __restrict__ hid1_mem0, const float* __restrict__ hid2_mem0,
    float* __restrict__ out)
{
    extern __shared__ float sm[];
    float*  w11  = sm;
    float*  w12  = w11 + 16384;
    float*  w22  = w12 + 16384;
    float*  b11s = w22 + 16384;
    float*  b12s = b11s + 128;
    float*  b22s = b12s + 128;
    unsigned int* s1w = (unsigned int*)(b22s + 128);
    unsigned int* s2w = s1w + 8;

    const int tid = threadIdx.x;
    const int h   = tid & 127;
    const int r   = tid >> 7;
    const int wi  = tid >> 5;
    const int l   = tid & 31;
    const int b   = blockIdx.x * 2 + r;

#pragma unroll 4
    for (int p = 0; p < 64; p++) {
        int i = p * 256 + tid;
        w11[i] = __fmul_rn(w_h1h1[i], mask[i]);
        w12[i] = w_h1h2[i];
        w22[i] = __fmul_rn(w_h2h2[i], mask[16384 + i]);
    }
    if (r == 0) {
        b11s[h] = b_h1h1[h];
        b12s[h] = b_h1h2[h];
        b22s[h] = b_h2h2[h];
    }
    if (tid < 16) s1w[tid] = 0u;

    const float a1 = exp_cr(__fdiv_rn(-1.0f, tau_m_h1[h]));
    const float r1 = exp_cr(__fdiv_rn(-1.0f, tau_adp_h1[h]));
    const float a2 = exp_cr(__fdiv_rn(-1.0f, tau_m_h2[h]));
    const float r2 = exp_cr(__fdiv_rn(-1.0f, tau_adp_h2[h]));
    const float oma1 = __fsub_rn(1.f, a1);
    const float omr1 = __fsub_rn(1.f, r1);
    const float oma2 = __fsub_rn(1.f, a2);
    const float omr2 = __fsub_rn(1.f, r2);

    float h1m = hid1_mem0[(size_t)b * 128 + h];
    float h2m = hid2_mem0[(size_t)b * 128 + h];
    float h1sp = 0.f, h2sp = 0.f;
    float bb1 = 0.01f, bb2 = 0.01f;
    float cnt1 = 0.f, cnt2 = 0.f;

    unsigned int u1[4] = {0u, 0u, 0u, 0u};
    unsigned int u2[4] = {0u, 0u, 0u, 0u};

    __syncthreads();

    const float* xin = g_xin + (size_t)b * TT * HH + h;
    float xa = xin[0];

    for (int t = 0; t < TT; t++) {
        float xan = (t + 1 < TT) ? xin[(size_t)(t + 1) * HH] : 0.f;

        float p1[4], p2[4];
#pragma unroll
        for (int w = 0; w < 4; w++) {
            const float* wp = w11 + (w << 12) + h;
            const float* wq = w22 + (w << 12) + h;
            float acc1 = 0.f, acc2 = 0.f;
            unsigned int d;
            d = u1[w];
            while (d) { int j = __ffs(d) - 1; d &= d - 1;
                        acc1 = __fadd_rn(acc1, wp[j << 7]); }
            d = u2[w];
            while (d) { int j = __ffs(d) - 1; d &= d - 1;
                        acc2 = __fadd_rn(acc2, wq[j << 7]); }
            p1[w] = acc1; p2[w] = acc2;
        }
        float m1  = __fadd_rn(__fadd_rn(__fadd_rn(p1[0], p1[1]), p1[2]), p1[3]);
        float m22 = __fadd_rn(__fadd_rn(__fadd_rn(p2[0], p2[1]), p2[2]), p2[3]);

        float i1 = __fadd_rn(__fadd_rn(xa, m1), b11s[h]);
        bb1 = __fadd_rn(__fmul_rn(r1, bb1), __fmul_rn(omr1, h1sp));
        float B1 = __fadd_rn(0.01f, __fmul_rn(1.8f, bb1));
        h1m = __fsub_rn(__fadd_rn(__fmul_rn(h1m, a1), __fmul_rn(oma1, i1)),
                        __fmul_rn(B1, h1sp));
        float s1n = (__fsub_rn(h1m, B1) > 0.f) ? 1.f : 0.f;
        cnt1 += s1n; h1sp = s1n;

        unsigned int wd1 = __ballot_sync(0xffffffffu, s1n != 0.f);
        if (l == 0) s1w[wi] = wd1;
        __syncthreads();

        unsigned int n1[4];
#pragma unroll
        for (int w = 0; w < 4; w++) n1[w] = s1w[(r << 2) + w];

        float q[4];
#pragma unroll
        for (int w = 0; w < 4; w++) {
            const float* wp = w12 + (w << 12) + h;
            float acc = 0.f;
            unsigned int d = n1[w];
            while (d) { int j = __ffs(d) - 1; d &= d - 1;
                        acc = __fadd_rn(acc, wp[j << 7]); }
            q[w] = acc;
        }
        float m12 = __fadd_rn(__fadd_rn(__fadd_rn(q[0], q[1]), q[2]), q[3]);

        float i2 = __fadd_rn(__fadd_rn(__fadd_rn(m12, b12s[h]), m22), b22s[h]);
        bb2 = __fadd_rn(__fmul_rn(r2, bb2), __fmul_rn(omr2, h2sp));
        float B2 = __fadd_rn(0.01f, __fmul_rn(1.8f, bb2));
        h2m = __fsub_rn(__fadd_rn(__fmul_rn(h2m, a2), __fmul_rn(oma2, i2)),
                        __fmul_rn(B2, h2sp));
        float s2n = (__fsub_rn(h2m, B2) > 0.f) ? 1.f : 0.f;
        cnt2 += s2n; h2sp = s2n;

        unsigned int wd2 = __ballot_sync(0xffffffffu, s2n != 0.f);
        if (l == 0) {
            s2w[wi] = wd2;
            g_spk[((size_t)b * TT + t) * 4 + (wi & 3)] = wd2;
        }
        __syncthreads();

#pragma unroll
        for (int w = 0; w < 4; w++) {
            u1[w] = n1[w];
            u2[w] = s2w[(r << 2) + w];
        }
        xa = xan;
    }

    const float T250 = 250.0f;
    out[5120 + (size_t)b * 128 + h]         = cnt1 / T250;
    out[5120 + 32768 + (size_t)b * 128 + h] = cnt2 / T250;
}

// ---------------------------------------------------------------------------
// Kernel 3: readout, RESTRUCTURED. Phase A: io dot (parallel) + cheap serial
// om recursion in warp 0 (no exp on the serial path), om written to smem.
// Phase B: softmax per t parallelized over all 128 threads (each t
// independent), per-thread partial accumulators, block tree-reduction.
// Per-t exp/sum/div orders identical to the R8-passing code; only the
// t-accumulation order changes (smooth sum, no downstream thresholds).
// ---------------------------------------------------------------------------
__global__ __launch_bounds__(128) void readout_kernel(
    const float* __restrict__ w_h2o, const float* __restrict__ b_h2o,
    const float* __restrict__ tau_m_o, const float* __restrict__ out_mem0,
    float* __restrict__ out)
{
    __shared__ float w2o_sm[128 * 20];
    __shared__ unsigned int spk[TT][4];
    __shared__ float om_sm[TT][20];      // io, overwritten by om in phase A
    __shared__ float red[128][20];

    const int b = blockIdx.x;
    const int tid = threadIdx.x;

    for (int i = tid; i < 128 * 20; i += 128) w2o_sm[i] = w_h2o[i];
    for (int i = tid; i < TT * 4; i += 128)
        ((unsigned int*)spk)[i] = g_spk[(size_t)b * TT * 4 + i];
    __syncthreads();

    // io[t][o] (parallel sparse dot, same as R9-R11 passing code)
    for (int p = tid; p < TT * 20; p += 128) {
        int t = p / 20;
        int o = p - t * 20;
        float acc = 0.f;
#pragma unroll
        for (int w = 0; w < 4; w++) {
            unsigned int word = spk[t][w];
            while (word) {
                int j = __ffs(word) - 1; word &= word - 1;
                acc = __fadd_rn(acc, w2o_sm[(w * 32 + j) * 20 + o]);
            }
        }
        om_sm[t][o] = acc;
    }
    __syncthreads();

    // Phase A: om recursion (serial over t, cheap — 2 mul + 2 add per step)
    if (tid < 32) {
        const int ll = tid;
        float om = 0.f, ao = 0.f, bo = 0.f;
        if (ll < 20) {
            om = out_mem0[(size_t)b * 20 + ll];
            ao = exp_cr(__fdiv_rn(-1.0f, tau_m_o[ll]));
            bo = b_h2o[ll];
        }
        const float omao = __fsub_rn(1.f, ao);
        for (int t = 0; t < TT; t++) {
            float iov = (ll < 20) ? __fadd_rn(om_sm[t][ll], bo) : 0.f;
            om = __fadd_rn(__fmul_rn(om, ao), __fmul_rn(omao, iov));
            if (ll < 20) om_sm[t][ll] = om;
        }
    }
    __syncthreads();

    // Phase B: softmax over t in parallel (t > 10 only)
    float acc[20];
#pragma unroll
    for (int o = 0; o < 20; o++) acc[o] = 0.f;

    for (int t = 11 + tid; t < TT; t += 128) {
        float omv[20];
#pragma unroll
        for (int o = 0; o < 20; o++) omv[o] = om_sm[t][o];
        // max: fmax is exact (no rounding) -> any order matches reference
        float v = omv[0];
#pragma unroll
        for (int o = 1; o < 20; o++) v = fmaxf(v, omv[o]);
        float e[20];
#pragma unroll
        for (int o = 0; o < 20; o++) e[o] = exp_cr(__fsub_rn(omv[o], v));
        // sum ascending o (same order as the passing R8 code)
        float ssum = 0.f;
#pragma unroll
        for (int o = 0; o < 20; o++) ssum = __fadd_rn(ssum, e[o]);
#pragma unroll
        for (int o = 0; o < 20; o++)
            acc[o] = __fadd_rn(acc[o], __fdiv_rn(e[o], ssum));
    }

#pragma unroll
    for (int o = 0; o < 20; o++) red[tid][o] = acc[o];
    __syncthreads();
#pragma unroll
    for (int s = 64; s > 0; s >>= 1) {
        if (tid < s) {
#pragma unroll
            for (int o = 0; o < 20; o++)
                red[tid][o] = __fadd_rn(red[tid][o], red[tid + s][o]);
        }
        __syncthreads();
    }
    if (tid < 20) out[(size_t)b * 20 + tid] = red[0][tid];
}

// ---------------------------------------------------------------------------
// Kernel 4: A_norm — unchanged (passed). Launched first.
// ---------------------------------------------------------------------------
__global__ __launch_bounds__(256) void anorm_kernel(
    const float* __restrict__ w_h1h1, const float* __restrict__ w_h2h2,
    const float* __restrict__ mask, float* __restrict__ out)
{
    __shared__ float red1[256];
    __shared__ float red2[256];
    int tid = threadIdx.x;
    float s1 = 0.f, s2 = 0.f;
    for (int i = tid; i < 16384; i += 256) {
        s1 = __fadd_rn(s1, fabsf(__fmul_rn(w_h1h1[i], mask[i])));
        s2 = __fadd_rn(s2, fabsf(__fmul_rn(w_h2h2[i], mask[16384 + i])));
    }
    red1[tid] = s1;
    red2[tid] = s2;
    __syncthreads();
#pragma unroll
    for (int st = 128; st > 0; st >>= 1) {
        if (tid < st) {
            red1[tid] = __fadd_rn(red1[tid], red1[tid + st]);
            red2[tid] = __fadd_rn(red2[tid], red2[tid + st]);
        }
        __syncthreads();
    }
    if (tid == 0) out[5120 + 2 * 32768] = __fadd_rn(red1[0], red2[0]);
}

// ---------------------------------------------------------------------------
extern "C" void kernel_launch(void* const* d_in, const int* in_sizes, int n_in,
                              void* d_out, int out_size)
{
    (void)in_sizes; (void)n_in; (void)out_size;
    const float* x          = (const float*)d_in[0];
    const float* mask       = (const float*)d_in[1];
    const float* w_ih1      = (const float*)d_in[2];
    const float* b_ih1      = (const float*)d_in[3];
    const float* w_h1h1     = (const float*)d_in[4];
    const float* b_h1h1     = (const float*)d_in[5];
    const float* w_h1h2     = (const float*)d_in[6];
    const float* b_h1h2     = (const float*)d_in[7];
    const float* w_h2h2     = (const float*)d_in[8];
    const float* b_h2h2     = (const float*)d_in[9];
    const float* w_h2o      = (const float*)d_in[10];
    const float* b_h2o      = (const float*)d_in[11];
    const float* tau_adp_h1 = (const float*)d_in[12];
    const float* tau_adp_h2 = (const float*)d_in[13];
    const float* tau_m_h1   = (const float*)d_in[14];
    const float* tau_m_h2   = (const float*)d_in[15];
    const float* tau_m_o    = (const float*)d_in[16];
    const float* hid1_mem0  = (const float*)d_in[17];
    const float* hid2_mem0  = (const float*)d_in[18];
    const float* out_mem0   = (const float*)d_in[19];
    float* out = (float*)d_out;

    anorm_kernel<<<1, 256>>>(w_h1h1, w_h2h2, mask, out);

    gemm_xin_kernel<<<(BT * TT) / 128, 256>>>(x, w_ih1, b_ih1);

    const int smem_bytes = SCAN_SMEM_FLOATS * (int)sizeof(float);
    cudaFuncSetAttribute(scan_kernel, cudaFuncAttributeMaxDynamicSharedMemorySize,
                         smem_bytes);
    scan_kernel<<<BT / 2, 256, smem_bytes>>>(
        mask, w_h1h1, b_h1h1, w_h1h2, b_h1h2, w_h2h2, b_h2h2,
        tau_adp_h1, tau_adp_h2, tau_m_h1, tau_m_h2,
        hid1_mem0, hid2_mem0, out);

    readout_kernel<<<BT, 128>>>(w_h2o, b_h2o, tau_m_o, out_mem0, out);
}

// round 14
// speedup vs baseline: 1.5391x; 1.1071x over previous
#include <cuda_runtime.h>
#include <cstdint>
#include <cstddef>

#define BT 256
#define TT 250
#define II 700
#define HH 128
#define OO 20

// Scratch: xin[b][t][h] = (x @ w_ih1 + b_ih1)
__device__ float g_xin[BT * TT * HH];
// layer-2 spike bit-words: [b][t][4]
__device__ unsigned int g_spk[BT * TT * 4];

// Correctly-rounded f32 exp (matches glibc scalar expf used by XLA:CPU).
// Used ONLY for the decay constants exp(-1/tau), whose ulps compound 250x.
__device__ __forceinline__ float exp_cr(float x) {
    return (float)exp((double)x);
}

// packed f32x2 helpers
__device__ __forceinline__ unsigned long long pack2(float lo, float hi) {
    unsigned long long r;
    asm("mov.b64 %0, {%1, %2};" : "=l"(r) : "f"(lo), "f"(hi));
    return r;
}
__device__ __forceinline__ void unpack2(unsigned long long v, float& lo, float& hi) {
    asm("mov.b64 {%0, %1}, %2;" : "=f"(lo), "=f"(hi) : "l"(v));
}
__device__ __forceinline__ void ffma2(unsigned long long& d, unsigned long long a,
                                      unsigned long long b) {
    asm("fma.rn.f32x2 %0, %1, %2, %0;" : "+l"(d) : "l"(a), "l"(b));
}

// ---------------------------------------------------------------------------
// Kernel 1: xin GEMM — unchanged from R10/R12 (passing numerics).
// ---------------------------------------------------------------------------
__global__ __launch_bounds__(256) void gemm_xin_kernel(
    const float* __restrict__ x, const float* __restrict__ w,
    const float* __restrict__ bias)
{
    __shared__ float a_sm[16][132];
    __shared__ float b_sm[16][128];

    const int tid = threadIdx.x;
    const int m0 = blockIdx.x * 128;
    const int tx = tid & 15, ty = tid >> 4;
    const int r0 = ty * 8;

    const int a_ml = tid >> 4, a_kl = tid & 15;
    const int b_kl = tid >> 7, b_hh = tid & 127;

    unsigned long long acc[8][4];
#pragma unroll
    for (int r = 0; r < 8; r++)
#pragma unroll
        for (int j = 0; j < 4; j++) acc[r][j] = 0ull;

    const int NT = (II + 15) / 16;
    float ra[8], rb[8];

    {
        int k0 = 0;
#pragma unroll
        for (int p = 0; p < 8; p++) {
            int k = k0 + a_kl;
            ra[p] = (k < II) ? x[(size_t)(m0 + a_ml + p * 16) * II + k] : 0.f;
        }
#pragma unroll
        for (int p = 0; p < 8; p++) {
            int k = k0 + b_kl + p * 2;
            rb[p] = (k < II) ? w[k * HH + b_hh] : 0.f;
        }
    }

    for (int kt = 0; kt < NT; kt++) {
#pragma unroll
        for (int p = 0; p < 8; p++) a_sm[a_kl][a_ml + p * 16] = ra[p];
#pragma unroll
        for (int p = 0; p < 8; p++) b_sm[b_kl + p * 2][b_hh] = rb[p];
        __syncthreads();

        if (kt + 1 < NT) {
            int k0 = (kt + 1) * 16;
#pragma unroll
            for (int p = 0; p < 8; p++) {
                int k = k0 + a_kl;
                ra[p] = (k < II) ? x[(size_t)(m0 + a_ml + p * 16) * II + k] : 0.f;
            }
#pragma unroll
            for (int p = 0; p < 8; p++) {
                int k = k0 + b_kl + p * 2;
                rb[p] = (k < II) ? w[k * HH + b_hh] : 0.f;
            }
        }

#pragma unroll
        for (int kk = 0; kk < 16; kk++) {
            float a[8];
            unsigned long long bb[4];
#pragma unroll
            for (int r = 0; r < 8; r++) a[r] = a_sm[kk][r0 + r];
            const float2* bp = reinterpret_cast<const float2*>(&b_sm[kk][2 * tx]);
#pragma unroll
            for (int j = 0; j < 4; j++) { float2 v = bp[16 * j]; bb[j] = pack2(v.x, v.y); }
#pragma unroll
            for (int r = 0; r < 8; r++) {
                unsigned long long ad = pack2(a[r], a[r]);
#pragma unroll
                for (int j = 0; j < 4; j++) ffma2(acc[r][j], ad, bb[j]);
            }
        }
        __syncthreads();
    }

#pragma unroll
    for (int r = 0; r < 8; r++) {
        int m = m0 + r0 + r;
#pragma unroll
        for (int j = 0; j < 4; j++) {
            float lo, hi;
            unpack2(acc[r][j], lo, hi);
            int c = 2 * tx + 32 * j;
            float2 v;
            v.x = __fadd_rn(lo, bias[c]);
            v.y = __fadd_rn(hi, bias[c + 1]);
            *reinterpret_cast<float2*>(&g_xin[(size_t)m * HH + c]) = v;
        }
    }
}

// ---------------------------------------------------------------------------
// Kernel 2: scan with INDEX LISTS. Each warp converts its own ballot word
// into an ascending index-list segment in smem (lane-parallel, no extra
// barriers; u1 lists double-buffered by step parity to avoid write races).
// Dots become fixed-trip loops over uint8 indices -> pipelinable loads,
// FADD chain 4cyc/bit. Single ascending-k accumulator per dot = R9 numerics.
// Still 2 barriers per step.
// ---------------------------------------------------------------------------
#define SCAN_SMEM_FLOATS (3 * 16384 + 3 * 128 + 24 + 192)

__global__ __launch_bounds__(256) void scan_kernel(
    const float* __restrict__ mask,
    const float* __restrict__ w_h1h1, const float* __restrict__ b_h1h1,
    const float* __restrict__ w_h1h2, const float* __restrict__ b_h1h2,
    const float* __restrict__ w_h2h2, const float* __restrict__ b_h2h2,
    const float* __restrict__ tau_adp_h1, const float* __restrict__ tau_adp_h2,
    const float* __restrict__ tau_m_h1,   const float* __restrict__ tau_m_h2,
    const float* __restrict__ hid1_mem0, const float* __restrict__ hid2_mem0,
    float* __restrict__ out)
{
    extern __shared__ float sm[];
    float*  w11  = sm;
    float*  w12  = w11 + 16384;
    float*  w22  = w12 + 16384;
    float*  b11s = w22 + 16384;
    float*  b12s = b11s + 128;
    float*  b22s = b12s + 128;
    int*      cntU1 = (int*)(b22s + 128);     // [2 par][2 row][4 word]
    int*      cnt2  = cntU1 + 16;             // [2 row][4 word]
    uint8_t*  lstU1 = (uint8_t*)(cnt2 + 8);   // [2 par][2 row][4 word][32]
    uint8_t*  lst2  = lstU1 + 512;            // [2 row][4 word][32]

    const int tid = threadIdx.x;
    const int h   = tid & 127;
    const int r   = tid >> 7;          // row within pair
    const int wi  = tid >> 5;          // warp 0..7: row = wi>>2, word = wi&3
    const int l   = tid & 31;
    const int myw = wi & 3;
    const int b   = blockIdx.x * 2 + r;

#pragma unroll 4
    for (int p = 0; p < 64; p++) {
        int i = p * 256 + tid;
        w11[i] = __fmul_rn(w_h1h1[i], mask[i]);
        w12[i] = w_h1h2[i];
        w22[i] = __fmul_rn(w_h2h2[i], mask[16384 + i]);
    }
    if (r == 0) {
        b11s[h] = b_h1h1[h];
        b12s[h] = b_h1h2[h];
        b22s[h] = b_h2h2[h];
    }
    if (tid < 24) cntU1[tid] = 0;   // zeroes cntU1[0..15] and cnt2[0..7]

    const float a1 = exp_cr(__fdiv_rn(-1.0f, tau_m_h1[h]));
    const float r1 = exp_cr(__fdiv_rn(-1.0f, tau_adp_h1[h]));
    const float a2 = exp_cr(__fdiv_rn(-1.0f, tau_m_h2[h]));
    const float r2 = exp_cr(__fdiv_rn(-1.0f, tau_adp_h2[h]));
    const float oma1 = __fsub_rn(1.f, a1);
    const float omr1 = __fsub_rn(1.f, r1);
    const float oma2 = __fsub_rn(1.f, a2);
    const float omr2 = __fsub_rn(1.f, r2);

    float h1m = hid1_mem0[(size_t)b * 128 + h];
    float h2m = hid2_mem0[(size_t)b * 128 + h];
    float h1sp = 0.f, h2sp = 0.f;
    float bb1 = 0.01f, bb2 = 0.01f;
    float cnt1c = 0.f, cnt2c = 0.f;

    __syncthreads();

    const float* xin = g_xin + (size_t)b * TT * HH + h;
    const float* w11h = w11 + h;
    const float* w12h = w12 + h;
    const float* w22h = w22 + h;
    float xa = xin[0];
    int p = 0;

    for (int t = 0; t < TT; t++) {
        float xan = (t + 1 < TT) ? xin[(size_t)(t + 1) * HH] : 0.f;

        // --- dot1 (w11 vs u1 list) + dot2 (w22 vs u2 list), ascending k ---
        float m1 = 0.f;
        {
            const int base = ((p * 2 + r) << 2);
#pragma unroll
            for (int w = 0; w < 4; w++) {
                int c = cntU1[base + w];
                const uint8_t* lp = lstU1 + ((base + w) << 5);
#pragma unroll 4
                for (int i = 0; i < c; i++)
                    m1 = __fadd_rn(m1, w11h[(int)lp[i] << 7]);
            }
        }
        float m22 = 0.f;
        {
            const int base = (r << 2);
#pragma unroll
            for (int w = 0; w < 4; w++) {
                int c = cnt2[base + w];
                const uint8_t* lp = lst2 + ((base + w) << 5);
#pragma unroll 4
                for (int i = 0; i < c; i++)
                    m22 = __fadd_rn(m22, w22h[(int)lp[i] << 7]);
            }
        }

        // --- layer 1 update (R8 elementwise numerics) ---
        float i1 = __fadd_rn(__fadd_rn(xa, m1), b11s[h]);
        bb1 = __fadd_rn(__fmul_rn(r1, bb1), __fmul_rn(omr1, h1sp));
        float B1 = __fadd_rn(0.01f, __fmul_rn(1.8f, bb1));
        h1m = __fsub_rn(__fadd_rn(__fmul_rn(h1m, a1), __fmul_rn(oma1, i1)),
                        __fmul_rn(B1, h1sp));
        float s1n = (__fsub_rn(h1m, B1) > 0.f) ? 1.f : 0.f;
        cnt1c += s1n; h1sp = s1n;

        // build next u1 list segment from this warp's own ballot word
        unsigned int wd1 = __ballot_sync(0xffffffffu, s1n != 0.f);
        {
            const int np = p ^ 1;
            const int slot = ((np * 2 + r) << 2) + myw;
            if ((wd1 >> l) & 1u) {
                int pos = __popc(wd1 & ((1u << l) - 1u));
                lstU1[(slot << 5) + pos] = (uint8_t)((myw << 5) | l);
            }
            if (l == 0) cntU1[slot] = __popc(wd1);
        }
        __syncthreads();

        // --- dot3 (w12 vs NEW layer-1 list) ---
        float m12 = 0.f;
        {
            const int base = (((p ^ 1) * 2 + r) << 2);
#pragma unroll
            for (int w = 0; w < 4; w++) {
                int c = cntU1[base + w];
                const uint8_t* lp = lstU1 + ((base + w) << 5);
#pragma unroll 4
                for (int i = 0; i < c; i++)
                    m12 = __fadd_rn(m12, w12h[(int)lp[i] << 7]);
            }
        }

        float i2 = __fadd_rn(__fadd_rn(__fadd_rn(m12, b12s[h]), m22), b22s[h]);
        bb2 = __fadd_rn(__fmul_rn(r2, bb2), __fmul_rn(omr2, h2sp));
        float B2 = __fadd_rn(0.01f, __fmul_rn(1.8f, bb2));
        h2m = __fsub_rn(__fadd_rn(__fmul_rn(h2m, a2), __fmul_rn(oma2, i2)),
                        __fmul_rn(B2, h2sp));
        float s2n = (__fsub_rn(h2m, B2) > 0.f) ? 1.f : 0.f;
        cnt2c += s2n; h2sp = s2n;

        unsigned int wd2 = __ballot_sync(0xffffffffu, s2n != 0.f);
        {
            const int slot = (r << 2) + myw;
            if ((wd2 >> l) & 1u) {
                int pos = __popc(wd2 & ((1u << l) - 1u));
                lst2[(slot << 5) + pos] = (uint8_t)((myw << 5) | l);
            }
            if (l == 0) {
                cnt2[slot] = __popc(wd2);
                g_spk[((size_t)b * TT + t) * 4 + myw] = wd2;
            }
        }
        __syncthreads();

        p ^= 1;
        xa = xan;
    }

    const float T250 = 250.0f;
    out[5120 + (size_t)b * 128 + h]         = cnt1c / T250;
    out[5120 + 32768 + (size_t)b * 128 + h] = cnt2c / T250;
}

// ---------------------------------------------------------------------------
// Kernel 3: readout. Phase A (serial om recursion) unchanged; Phase B softmax
// now uses fp32 expf (no compounding, no thresholds downstream — ulp-scale
// output shift only). Decay constant ao stays exp_cr.
// ---------------------------------------------------------------------------
__global__ __launch_bounds__(128) void readout_kernel(
    const float* __restrict__ w_h2o, const float* __restrict__ b_h2o,
    const float* __restrict__ tau_m_o, const float* __restrict__ out_mem0,
    float* __restrict__ out)
{
    __shared__ float w2o_sm[128 * 20];
    __shared__ unsigned int spk[TT][4];
    __shared__ float om_sm[TT][20];
    __shared__ float red[128][20];

    const int b = blockIdx.x;
    const int tid = threadIdx.x;

    for (int i = tid; i < 128 * 20; i += 128) w2o_sm[i] = w_h2o[i];
    for (int i = tid; i < TT * 4; i += 128)
        ((unsigned int*)spk)[i] = g_spk[(size_t)b * TT * 4 + i];
    __syncthreads();

    for (int pidx = tid; pidx < TT * 20; pidx += 128) {
        int t = pidx / 20;
        int o = pidx - t * 20;
        float acc = 0.f;
#pragma unroll
        for (int w = 0; w < 4; w++) {
            unsigned int word = spk[t][w];
            while (word) {
                int j = __ffs(word) - 1; word &= word - 1;
                acc = __fadd_rn(acc, w2o_sm[(w * 32 + j) * 20 + o]);
            }
        }
        om_sm[t][o] = acc;
    }
    __syncthreads();

    if (tid < 32) {
        const int ll = tid;
        float om = 0.f, ao = 0.f, bo = 0.f;
        if (ll < 20) {
            om = out_mem0[(size_t)b * 20 + ll];
            ao = exp_cr(__fdiv_rn(-1.0f, tau_m_o[ll]));
            bo = b_h2o[ll];
        }
        const float omao = __fsub_rn(1.f, ao);
        for (int t = 0; t < TT; t++) {
            float iov = (ll < 20) ? __fadd_rn(om_sm[t][ll], bo) : 0.f;
            om = __fadd_rn(__fmul_rn(om, ao), __fmul_rn(omao, iov));
            if (ll < 20) om_sm[t][ll] = om;
        }
    }
    __syncthreads();

    float acc[20];
#pragma unroll
    for (int o = 0; o < 20; o++) acc[o] = 0.f;

    for (int t = 11 + tid; t < TT; t += 128) {
        float omv[20];
#pragma unroll
        for (int o = 0; o < 20; o++) omv[o] = om_sm[t][o];
        float v = omv[0];
#pragma unroll
        for (int o = 1; o < 20; o++) v = fmaxf(v, omv[o]);
        float e[20];
#pragma unroll
        for (int o = 0; o < 20; o++) e[o] = expf(__fsub_rn(omv[o], v));
        float ssum = 0.f;
#pragma unroll
        for (int o = 0; o < 20; o++) ssum = __fadd_rn(ssum, e[o]);
#pragma unroll
        for (int o = 0; o < 20; o++)
            acc[o] = __fadd_rn(acc[o], __fdiv_rn(e[o], ssum));
    }

#pragma unroll
    for (int o = 0; o < 20; o++) red[tid][o] = acc[o];
    __syncthreads();
#pragma unroll
    for (int s = 64; s > 0; s >>= 1) {
        if (tid < s) {
#pragma unroll
            for (int o = 0; o < 20; o++)
                red[tid][o] = __fadd_rn(red[tid][o], red[tid + s][o]);
        }
        __syncthreads();
    }
    if (tid < 20) out[(size_t)b * 20 + tid] = red[0][tid];
}

// ---------------------------------------------------------------------------
// Kernel 4: A_norm — unchanged. Launched first.
// ---------------------------------------------------------------------------
__global__ __launch_bounds__(256) void anorm_kernel(
    const float* __restrict__ w_h1h1, const float* __restrict__ w_h2h2,
    const float* __restrict__ mask, float* __restrict__ out)
{
    __shared__ float red1[256];
    __shared__ float red2[256];
    int tid = threadIdx.x;
    float s1 = 0.f, s2 = 0.f;
    for (int i = tid; i < 16384; i += 256) {
        s1 = __fadd_rn(s1, fabsf(__fmul_rn(w_h1h1[i], mask[i])));
        s2 = __fadd_rn(s2, fabsf(__fmul_rn(w_h2h2[i], mask[16384 + i])));
    }
    red1[tid] = s1;
    red2[tid] = s2;
    __syncthreads();
#pragma unroll
    for (int st = 128; st > 0; st >>= 1) {
        if (tid < st) {
            red1[tid] = __fadd_rn(red1[tid], red1[tid + st]);
            red2[tid] = __fadd_rn(red2[tid], red2[tid + st]);
        }
        __syncthreads();
    }
    if (tid == 0) out[5120 + 2 * 32768] = __fadd_rn(red1[0], red2[0]);
}

// ---------------------------------------------------------------------------
extern "C" void kernel_launch(void* const* d_in, const int* in_sizes, int n_in,
                              void* d_out, int out_size)
{
    (void)in_sizes; (void)n_in; (void)out_size;
    const float* x          = (const float*)d_in[0];
    const float* mask       = (const float*)d_in[1];
    const float* w_ih1      = (const float*)d_in[2];
    const float* b_ih1      = (const float*)d_in[3];
    const float* w_h1h1     = (const float*)d_in[4];
    const float* b_h1h1     = (const float*)d_in[5];
    const float* w_h1h2     = (const float*)d_in[6];
    const float* b_h1h2     = (const float*)d_in[7];
    const float* w_h2h2     = (const float*)d_in[8];
    const float* b_h2h2     = (const float*)d_in[9];
    const float* w_h2o      = (const float*)d_in[10];
    const float* b_h2o      = (const float*)d_in[11];
    const float* tau_adp_h1 = (const float*)d_in[12];
    const float* tau_adp_h2 = (const float*)d_in[13];
    const float* tau_m_h1   = (const float*)d_in[14];
    const float* tau_m_h2   = (const float*)d_in[15];
    const float* tau_m_o    = (const float*)d_in[16];
    const float* hid1_mem0  = (const float*)d_in[17];
    const float* hid2_mem0  = (const float*)d_in[18];
    const float* out_mem0   = (const float*)d_in[19];
    float* out = (float*)d_out;

    anorm_kernel<<<1, 256>>>(w_h1h1, w_h2h2, mask, out);

    gemm_xin_kernel<<<(BT * TT) / 128, 256>>>(x, w_ih1, b_ih1);

    const int smem_bytes = SCAN_SMEM_FLOATS * (int)sizeof(float);
    cudaFuncSetAttribute(scan_kernel, cudaFuncAttributeMaxDynamicSharedMemorySize,
                         smem_bytes);
    scan_kernel<<<BT / 2, 256, smem_bytes>>>(
        mask, w_h1h1, b_h1h1, w_h1h2, b_h1h2, w_h2h2, b_h2h2,
        tau_adp_h1, tau_adp_h2, tau_m_h1, tau_m_h2,
        hid1_mem0, hid2_mem0, out);

    readout_kernel<<<BT, 128>>>(w_h2o, b_h2o, tau_m_o, out_mem0, out);
}

// round 15
// speedup vs baseline: 1.6009x; 1.0401x over previous
#include <cuda_runtime.h>
#include <cstdint>
#include <cstddef>

#define BT 256
#define TT 250
#define II 700
#define HH 128
#define OO 20

// Scratch: xin[b][t][h] = (x @ w_ih1 + b_ih1)
__device__ float g_xin[BT * TT * HH];
// layer-2 spike bit-words: [b][t][4]
__device__ unsigned int g_spk[BT * TT * 4];

// Correctly-rounded f32 exp (matches glibc scalar expf used by XLA:CPU).
// Used ONLY for the decay constants exp(-1/tau), whose ulps compound 250x.
__device__ __forceinline__ float exp_cr(float x) {
    return (float)exp((double)x);
}

// packed f32x2 helpers
__device__ __forceinline__ unsigned long long pack2(float lo, float hi) {
    unsigned long long r;
    asm("mov.b64 %0, {%1, %2};" : "=l"(r) : "f"(lo), "f"(hi));
    return r;
}
__device__ __forceinline__ void unpack2(unsigned long long v, float& lo, float& hi) {
    asm("mov.b64 {%0, %1}, %2;" : "=f"(lo), "=f"(hi) : "l"(v));
}
__device__ __forceinline__ void ffma2(unsigned long long& d, unsigned long long a,
                                      unsigned long long b) {
    asm("fma.rn.f32x2 %0, %1, %2, %0;" : "+l"(d) : "l"(a), "l"(b));
}

// ---------------------------------------------------------------------------
// Kernel 1: xin GEMM — unchanged (near fp32 roofline, ~160us floor).
// ---------------------------------------------------------------------------
__global__ __launch_bounds__(256) void gemm_xin_kernel(
    const float* __restrict__ x, const float* __restrict__ w,
    const float* __restrict__ bias)
{
    __shared__ float a_sm[16][132];
    __shared__ float b_sm[16][128];

    const int tid = threadIdx.x;
    const int m0 = blockIdx.x * 128;
    const int tx = tid & 15, ty = tid >> 4;
    const int r0 = ty * 8;

    const int a_ml = tid >> 4, a_kl = tid & 15;
    const int b_kl = tid >> 7, b_hh = tid & 127;

    unsigned long long acc[8][4];
#pragma unroll
    for (int r = 0; r < 8; r++)
#pragma unroll
        for (int j = 0; j < 4; j++) acc[r][j] = 0ull;

    const int NT = (II + 15) / 16;
    float ra[8], rb[8];

    {
        int k0 = 0;
#pragma unroll
        for (int p = 0; p < 8; p++) {
            int k = k0 + a_kl;
            ra[p] = (k < II) ? x[(size_t)(m0 + a_ml + p * 16) * II + k] : 0.f;
        }
#pragma unroll
        for (int p = 0; p < 8; p++) {
            int k = k0 + b_kl + p * 2;
            rb[p] = (k < II) ? w[k * HH + b_hh] : 0.f;
        }
    }

    for (int kt = 0; kt < NT; kt++) {
#pragma unroll
        for (int p = 0; p < 8; p++) a_sm[a_kl][a_ml + p * 16] = ra[p];
#pragma unroll
        for (int p = 0; p < 8; p++) b_sm[b_kl + p * 2][b_hh] = rb[p];
        __syncthreads();

        if (kt + 1 < NT) {
            int k0 = (kt + 1) * 16;
#pragma unroll
            for (int p = 0; p < 8; p++) {
                int k = k0 + a_kl;
                ra[p] = (k < II) ? x[(size_t)(m0 + a_ml + p * 16) * II + k] : 0.f;
            }
#pragma unroll
            for (int p = 0; p < 8; p++) {
                int k = k0 + b_kl + p * 2;
                rb[p] = (k < II) ? w[k * HH + b_hh] : 0.f;
            }
        }

#pragma unroll
        for (int kk = 0; kk < 16; kk++) {
            float a[8];
            unsigned long long bb[4];
#pragma unroll
            for (int r = 0; r < 8; r++) a[r] = a_sm[kk][r0 + r];
            const float2* bp = reinterpret_cast<const float2*>(&b_sm[kk][2 * tx]);
#pragma unroll
            for (int j = 0; j < 4; j++) { float2 v = bp[16 * j]; bb[j] = pack2(v.x, v.y); }
#pragma unroll
            for (int r = 0; r < 8; r++) {
                unsigned long long ad = pack2(a[r], a[r]);
#pragma unroll
                for (int j = 0; j < 4; j++) ffma2(acc[r][j], ad, bb[j]);
            }
        }
        __syncthreads();
    }

#pragma unroll
    for (int r = 0; r < 8; r++) {
        int m = m0 + r0 + r;
#pragma unroll
        for (int j = 0; j < 4; j++) {
            float lo, hi;
            unpack2(acc[r][j], lo, hi);
            int c = 2 * tx + 32 * j;
            float2 v;
            v.x = __fadd_rn(lo, bias[c]);
            v.y = __fadd_rn(hi, bias[c + 1]);
            *reinterpret_cast<float2*>(&g_xin[(size_t)m * HH + c]) = v;
        }
    }
}

// ---------------------------------------------------------------------------
// Kernel 2: scan, 512 threads (16 warps), warp-specialized dots:
//   primaries (half==0) own the state, compute FULL dot1 chain (= R14 order),
//   helpers (half==1) concurrently compute FULL dot2 chain (= R14 order) and
//   the upper half of dot3. dot3 = (chain(seg0,seg1)) + (chain(seg2,seg3))
//   — R6-proven-safe re-association. 3 barriers/step.
// ---------------------------------------------------------------------------
#define SCAN_SMEM_FLOATS (3 * 16384 + 3 * 128 + 512 + 24 + 192)

__global__ __launch_bounds__(512) void scan_kernel(
    const float* __restrict__ mask,
    const float* __restrict__ w_h1h1, const float* __restrict__ b_h1h1,
    const float* __restrict__ w_h1h2, const float* __restrict__ b_h1h2,
    const float* __restrict__ w_h2h2, const float* __restrict__ b_h2h2,
    const float* __restrict__ tau_adp_h1, const float* __restrict__ tau_adp_h2,
    const float* __restrict__ tau_m_h1,   const float* __restrict__ tau_m_h2,
    const float* __restrict__ hid1_mem0, const float* __restrict__ hid2_mem0,
    float* __restrict__ out)
{
    extern __shared__ float sm[];
    float*  w11  = sm;
    float*  w12  = w11 + 16384;
    float*  w22  = w12 + 16384;
    float*  b11s = w22 + 16384;
    float*  b12s = b11s + 128;
    float*  b22s = b12s + 128;
    float*  pm22 = b22s + 128;                // [2 row][128]
    float*  pm12 = pm22 + 256;                // [2 row][128]
    int*      cntU1 = (int*)(pm12 + 256);     // [2 par][2 row][4 word]
    int*      cnt2  = cntU1 + 16;             // [2 row][4 word]
    uint8_t*  lstU1 = (uint8_t*)(cnt2 + 8);   // [2 par][2 row][4 word][32]
    uint8_t*  lst2  = lstU1 + 512;            // [2 row][4 word][32]

    const int tid  = threadIdx.x;
    const int h    = tid & 127;
    const int half = (tid >> 7) & 1;
    const int r    = tid >> 8;
    const int wi   = tid >> 5;
    const int l    = tid & 31;
    const int myw  = wi & 3;
    const int b    = blockIdx.x * 2 + r;

#pragma unroll 4
    for (int p_ = 0; p_ < 32; p_++) {
        int i = p_ * 512 + tid;
        w11[i] = __fmul_rn(w_h1h1[i], mask[i]);
        w12[i] = w_h1h2[i];
        w22[i] = __fmul_rn(w_h2h2[i], mask[16384 + i]);
    }
    if (tid < 128) {
        b11s[tid] = b_h1h1[tid];
        b12s[tid] = b_h1h2[tid];
        b22s[tid] = b_h2h2[tid];
    }
    if (tid < 24) cntU1[tid] = 0;

    const float a1 = exp_cr(__fdiv_rn(-1.0f, tau_m_h1[h]));
    const float r1 = exp_cr(__fdiv_rn(-1.0f, tau_adp_h1[h]));
    const float a2 = exp_cr(__fdiv_rn(-1.0f, tau_m_h2[h]));
    const float r2 = exp_cr(__fdiv_rn(-1.0f, tau_adp_h2[h]));
    const float oma1 = __fsub_rn(1.f, a1);
    const float omr1 = __fsub_rn(1.f, r1);
    const float oma2 = __fsub_rn(1.f, a2);
    const float omr2 = __fsub_rn(1.f, r2);

    float h1m = hid1_mem0[(size_t)b * 128 + h];
    float h2m = hid2_mem0[(size_t)b * 128 + h];
    float h1sp = 0.f, h2sp = 0.f;
    float bb1 = 0.01f, bb2 = 0.01f;
    float cnt1c = 0.f, cnt2c = 0.f;

    __syncthreads();

    const float* xin  = g_xin + (size_t)b * TT * HH + h;
    const float* w11h = w11 + h;
    const float* w12h = w12 + h;
    const float* w22h = w22 + h;
    float xa = (half == 0) ? xin[0] : 0.f;
    int p = 0;

    for (int t = 0; t < TT; t++) {
        float xan = 0.f;
        if (half == 0) {
            if (t + 1 < TT) xan = xin[(size_t)(t + 1) * HH];

            // --- dot1: full ascending chain over u1 lists (R14 order) ---
            float m1 = 0.f;
            const int base = ((p * 2 + r) << 2);
#pragma unroll
            for (int w = 0; w < 4; w++) {
                int c = cntU1[base + w];
                const uint8_t* lp = lstU1 + ((base + w) << 5);
#pragma unroll 4
                for (int i = 0; i < c; i++)
                    m1 = __fadd_rn(m1, w11h[(int)lp[i] << 7]);
            }

            // --- layer 1 update (R8 elementwise numerics) ---
            float i1 = __fadd_rn(__fadd_rn(xa, m1), b11s[h]);
            bb1 = __fadd_rn(__fmul_rn(r1, bb1), __fmul_rn(omr1, h1sp));
            float B1 = __fadd_rn(0.01f, __fmul_rn(1.8f, bb1));
            h1m = __fsub_rn(__fadd_rn(__fmul_rn(h1m, a1), __fmul_rn(oma1, i1)),
                            __fmul_rn(B1, h1sp));
            float s1n = (__fsub_rn(h1m, B1) > 0.f) ? 1.f : 0.f;
            cnt1c += s1n; h1sp = s1n;

            unsigned int wd1 = __ballot_sync(0xffffffffu, s1n != 0.f);
            const int np = p ^ 1;
            const int slot = ((np * 2 + r) << 2) + myw;
            if ((wd1 >> l) & 1u) {
                int pos = __popc(wd1 & ((1u << l) - 1u));
                lstU1[(slot << 5) + pos] = (uint8_t)((myw << 5) | l);
            }
            if (l == 0) cntU1[slot] = __popc(wd1);
        } else {
            // --- helper: dot2 full ascending chain (R14 order) ---
            float m22 = 0.f;
            const int base2 = (r << 2);
#pragma unroll
            for (int w = 0; w < 4; w++) {
                int c = cnt2[base2 + w];
                const uint8_t* lp = lst2 + ((base2 + w) << 5);
#pragma unroll 4
                for (int i = 0; i < c; i++)
                    m22 = __fadd_rn(m22, w22h[(int)lp[i] << 7]);
            }
            pm22[(r << 7) + h] = m22;
        }
        __syncthreads();   // A: new u1 lists + pm22 visible

        // --- dot3 split: primary segs 0-1, helper segs 2-3 ---
        float q = 0.f;
        {
            const int base = ((((p ^ 1) * 2 + r) << 2)) + half * 2;
#pragma unroll
            for (int w = 0; w < 2; w++) {
                int c = cntU1[base + w];
                const uint8_t* lp = lstU1 + ((base + w) << 5);
#pragma unroll 4
                for (int i = 0; i < c; i++)
                    q = __fadd_rn(q, w12h[(int)lp[i] << 7]);
            }
        }
        if (half) pm12[(r << 7) + h] = q;
        __syncthreads();   // B: pm12 visible

        if (half == 0) {
            float m12 = __fadd_rn(q, pm12[(r << 7) + h]);
            float m22 = pm22[(r << 7) + h];
            float i2 = __fadd_rn(__fadd_rn(__fadd_rn(m12, b12s[h]), m22), b22s[h]);
            bb2 = __fadd_rn(__fmul_rn(r2, bb2), __fmul_rn(omr2, h2sp));
            float B2 = __fadd_rn(0.01f, __fmul_rn(1.8f, bb2));
            h2m = __fsub_rn(__fadd_rn(__fmul_rn(h2m, a2), __fmul_rn(oma2, i2)),
                            __fmul_rn(B2, h2sp));
            float s2n = (__fsub_rn(h2m, B2) > 0.f) ? 1.f : 0.f;
            cnt2c += s2n; h2sp = s2n;

            unsigned int wd2 = __ballot_sync(0xffffffffu, s2n != 0.f);
            const int slot = (r << 2) + myw;
            if ((wd2 >> l) & 1u) {
                int pos = __popc(wd2 & ((1u << l) - 1u));
                lst2[(slot << 5) + pos] = (uint8_t)((myw << 5) | l);
            }
            if (l == 0) {
                cnt2[slot] = __popc(wd2);
                g_spk[((size_t)b * TT + t) * 4 + myw] = wd2;
            }
            xa = xan;
        }
        __syncthreads();   // C: new lst2 visible for next step's dot2

        p ^= 1;
    }

    if (half == 0) {
        const float T250 = 250.0f;
        out[5120 + (size_t)b * 128 + h]         = cnt1c / T250;
        out[5120 + 32768 + (size_t)b * 128 + h] = cnt2c / T250;
    }
}

// ---------------------------------------------------------------------------
// Kernel 3: readout — unchanged from R14 (43us, passing).
// ---------------------------------------------------------------------------
__global__ __launch_bounds__(128) void readout_kernel(
    const float* __restrict__ w_h2o, const float* __restrict__ b_h2o,
    const float* __restrict__ tau_m_o, const float* __restrict__ out_mem0,
    float* __restrict__ out)
{
    __shared__ float w2o_sm[128 * 20];
    __shared__ unsigned int spk[TT][4];
    __shared__ float om_sm[TT][20];
    __shared__ float red[128][20];

    const int b = blockIdx.x;
    const int tid = threadIdx.x;

    for (int i = tid; i < 128 * 20; i += 128) w2o_sm[i] = w_h2o[i];
    for (int i = tid; i < TT * 4; i += 128)
        ((unsigned int*)spk)[i] = g_spk[(size_t)b * TT * 4 + i];
    __syncthreads();

    for (int pidx = tid; pidx < TT * 20; pidx += 128) {
        int t = pidx / 20;
        int o = pidx - t * 20;
        float acc = 0.f;
#pragma unroll
        for (int w = 0; w < 4; w++) {
            unsigned int word = spk[t][w];
            while (word) {
                int j = __ffs(word) - 1; word &= word - 1;
                acc = __fadd_rn(acc, w2o_sm[(w * 32 + j) * 20 + o]);
            }
        }
        om_sm[t][o] = acc;
    }
    __syncthreads();

    if (tid < 32) {
        const int ll = tid;
        float om = 0.f, ao = 0.f, bo = 0.f;
        if (ll < 20) {
            om = out_mem0[(size_t)b * 20 + ll];
            ao = exp_cr(__fdiv_rn(-1.0f, tau_m_o[ll]));
            bo = b_h2o[ll];
        }
        const float omao = __fsub_rn(1.f, ao);
        for (int t = 0; t < TT; t++) {
            float iov = (ll < 20) ? __fadd_rn(om_sm[t][ll], bo) : 0.f;
            om = __fadd_rn(__fmul_rn(om, ao), __fmul_rn(omao, iov));
            if (ll < 20) om_sm[t][ll] = om;
        }
    }
    __syncthreads();

    float acc[20];
#pragma unroll
    for (int o = 0; o < 20; o++) acc[o] = 0.f;

    for (int t = 11 + tid; t < TT; t += 128) {
        float omv[20];
#pragma unroll
        for (int o = 0; o < 20; o++) omv[o] = om_sm[t][o];
        float v = omv[0];
#pragma unroll
        for (int o = 1; o < 20; o++) v = fmaxf(v, omv[o]);
        float e[20];
#pragma unroll
        for (int o = 0; o < 20; o++) e[o] = expf(__fsub_rn(omv[o], v));
        float ssum = 0.f;
#pragma unroll
        for (int o = 0; o < 20; o++) ssum = __fadd_rn(ssum, e[o]);
#pragma unroll
        for (int o = 0; o < 20; o++)
            acc[o] = __fadd_rn(acc[o], __fdiv_rn(e[o], ssum));
    }

#pragma unroll
    for (int o = 0; o < 20; o++) red[tid][o] = acc[o];
    __syncthreads();
#pragma unroll
    for (int s = 64; s > 0; s >>= 1) {
        if (tid < s) {
#pragma unroll
            for (int o = 0; o < 20; o++)
                red[tid][o] = __fadd_rn(red[tid][o], red[tid + s][o]);
        }
        __syncthreads();
    }
    if (tid < 20) out[(size_t)b * 20 + tid] = red[0][tid];
}

// ---------------------------------------------------------------------------
// Kernel 4: A_norm — unchanged. Launched first.
// ---------------------------------------------------------------------------
__global__ __launch_bounds__(256) void anorm_kernel(
    const float* __restrict__ w_h1h1, const float* __restrict__ w_h2h2,
    const float* __restrict__ mask, float* __restrict__ out)
{
    __shared__ float red1[256];
    __shared__ float red2[256];
    int tid = threadIdx.x;
    float s1 = 0.f, s2 = 0.f;
    for (int i = tid; i < 16384; i += 256) {
        s1 = __fadd_rn(s1, fabsf(__fmul_rn(w_h1h1[i], mask[i])));
        s2 = __fadd_rn(s2, fabsf(__fmul_rn(w_h2h2[i], mask[16384 + i])));
    }
    red1[tid] = s1;
    red2[tid] = s2;
    __syncthreads();
#pragma unroll
    for (int st = 128; st > 0; st >>= 1) {
        if (tid < st) {
            red1[tid] = __fadd_rn(red1[tid], red1[tid + st]);
            red2[tid] = __fadd_rn(red2[tid], red2[tid + st]);
        }
        __syncthreads();
    }
    if (tid == 0) out[5120 + 2 * 32768] = __fadd_rn(red1[0], red2[0]);
}

// Marker no-op: shifts the fixed ncu capture window onto the scan (4th launch).
__global__ void marker_kernel() {}

// ---------------------------------------------------------------------------
extern "C" void kernel_launch(void* const* d_in, const int* in_sizes, int n_in,
                              void* d_out, int out_size)
{
    (void)in_sizes; (void)n_in; (void)out_size;
    const float* x          = (const float*)d_in[0];
    const float* mask       = (const float*)d_in[1];
    const float* w_ih1      = (const float*)d_in[2];
    const float* b_ih1      = (const float*)d_in[3];
    const float* w_h1h1     = (const float*)d_in[4];
    const float* b_h1h1     = (const float*)d_in[5];
    const float* w_h1h2     = (const float*)d_in[6];
    const float* b_h1h2     = (const float*)d_in[7];
    const float* w_h2h2     = (const float*)d_in[8];
    const float* b_h2h2     = (const float*)d_in[9];
    const float* w_h2o      = (const float*)d_in[10];
    const float* b_h2o      = (const float*)d_in[11];
    const float* tau_adp_h1 = (const float*)d_in[12];
    const float* tau_adp_h2 = (const float*)d_in[13];
    const float* tau_m_h1   = (const float*)d_in[14];
    const float* tau_m_h2   = (const float*)d_in[15];
    const float* tau_m_o    = (const float*)d_in[16];
    const float* hid1_mem0  = (const float*)d_in[17];
    const float* hid2_mem0  = (const float*)d_in[18];
    const float* out_mem0   = (const float*)d_in[19];
    float* out = (float*)d_out;

    anorm_kernel<<<1, 256>>>(w_h1h1, w_h2h2, mask, out);

    gemm_xin_kernel<<<(BT * TT) / 128, 256>>>(x, w_ih1, b_ih1);

    marker_kernel<<<1, 32>>>();

    const int smem_bytes = SCAN_SMEM_FLOATS * (int)sizeof(float);
    cudaFuncSetAttribute(scan_kernel, cudaFuncAttributeMaxDynamicSharedMemorySize,
                         smem_bytes);
    scan_kernel<<<BT / 2, 512, smem_bytes>>>(
        mask, w_h1h1, b_h1h1, w_h1h2, b_h1h2, w_h2h2, b_h2h2,
        tau_adp_h1, tau_adp_h2, tau_m_h1, tau_m_h2,
        hid1_mem0, hid2_mem0, out);

    readout_kernel<<<BT, 128>>>(w_h2o, b_h2o, tau_m_o, out_mem0, out);
}

// round 16
// speedup vs baseline: 1.7483x; 1.0921x over previous
#include <cuda_runtime.h>
#include <cstdint>
#include <cstddef>

#define BT 256
#define TT 250
#define II 700
#define HH 128
#define OO 20

// Scratch: xin[b][t][h] = (x @ w_ih1 + b_ih1)
__device__ float g_xin[BT * TT * HH];
// layer-2 spike bit-words: [b][t][4]
__device__ unsigned int g_spk[BT * TT * 4];

// Correctly-rounded f32 exp (matches glibc scalar expf used by XLA:CPU).
__device__ __forceinline__ float exp_cr(float x) {
    return (float)exp((double)x);
}

// packed f32x2 helpers
__device__ __forceinline__ unsigned long long pack2(float lo, float hi) {
    unsigned long long r;
    asm("mov.b64 %0, {%1, %2};" : "=l"(r) : "f"(lo), "f"(hi));
    return r;
}
__device__ __forceinline__ void unpack2(unsigned long long v, float& lo, float& hi) {
    asm("mov.b64 {%0, %1}, %2;" : "=f"(lo), "=f"(hi) : "l"(v));
}
__device__ __forceinline__ void ffma2(unsigned long long& d, unsigned long long a,
                                      unsigned long long b) {
    asm("fma.rn.f32x2 %0, %1, %2, %0;" : "+l"(d) : "l"(a), "l"(b));
}

// ---------------------------------------------------------------------------
// Kernel 1: xin GEMM — unchanged (near fp32 roofline).
// ---------------------------------------------------------------------------
__global__ __launch_bounds__(256) void gemm_xin_kernel(
    const float* __restrict__ x, const float* __restrict__ w,
    const float* __restrict__ bias)
{
    __shared__ float a_sm[16][132];
    __shared__ float b_sm[16][128];

    const int tid = threadIdx.x;
    const int m0 = blockIdx.x * 128;
    const int tx = tid & 15, ty = tid >> 4;
    const int r0 = ty * 8;

    const int a_ml = tid >> 4, a_kl = tid & 15;
    const int b_kl = tid >> 7, b_hh = tid & 127;

    unsigned long long acc[8][4];
#pragma unroll
    for (int r = 0; r < 8; r++)
#pragma unroll
        for (int j = 0; j < 4; j++) acc[r][j] = 0ull;

    const int NT = (II + 15) / 16;
    float ra[8], rb[8];

    {
        int k0 = 0;
#pragma unroll
        for (int p = 0; p < 8; p++) {
            int k = k0 + a_kl;
            ra[p] = (k < II) ? x[(size_t)(m0 + a_ml + p * 16) * II + k] : 0.f;
        }
#pragma unroll
        for (int p = 0; p < 8; p++) {
            int k = k0 + b_kl + p * 2;
            rb[p] = (k < II) ? w[k * HH + b_hh] : 0.f;
        }
    }

    for (int kt = 0; kt < NT; kt++) {
#pragma unroll
        for (int p = 0; p < 8; p++) a_sm[a_kl][a_ml + p * 16] = ra[p];
#pragma unroll
        for (int p = 0; p < 8; p++) b_sm[b_kl + p * 2][b_hh] = rb[p];
        __syncthreads();

        if (kt + 1 < NT) {
            int k0 = (kt + 1) * 16;
#pragma unroll
            for (int p = 0; p < 8; p++) {
                int k = k0 + a_kl;
                ra[p] = (k < II) ? x[(size_t)(m0 + a_ml + p * 16) * II + k] : 0.f;
            }
#pragma unroll
            for (int p = 0; p < 8; p++) {
                int k = k0 + b_kl + p * 2;
                rb[p] = (k < II) ? w[k * HH + b_hh] : 0.f;
            }
        }

#pragma unroll
        for (int kk = 0; kk < 16; kk++) {
            float a[8];
            unsigned long long bb[4];
#pragma unroll
            for (int r = 0; r < 8; r++) a[r] = a_sm[kk][r0 + r];
            const float2* bp = reinterpret_cast<const float2*>(&b_sm[kk][2 * tx]);
#pragma unroll
            for (int j = 0; j < 4; j++) { float2 v = bp[16 * j]; bb[j] = pack2(v.x, v.y); }
#pragma unroll
            for (int r = 0; r < 8; r++) {
                unsigned long long ad = pack2(a[r], a[r]);
#pragma unroll
                for (int j = 0; j < 4; j++) ffma2(acc[r][j], ad, bb[j]);
            }
        }
        __syncthreads();
    }

#pragma unroll
    for (int r = 0; r < 8; r++) {
        int m = m0 + r0 + r;
#pragma unroll
        for (int j = 0; j < 4; j++) {
            float lo, hi;
            unpack2(acc[r][j], lo, hi);
            int c = 2 * tx + 32 * j;
            float2 v;
            v.x = __fadd_rn(lo, bias[c]);
            v.y = __fadd_rn(hi, bias[c + 1]);
            *reinterpret_cast<float2*>(&g_xin[(size_t)m * HH + c]) = v;
        }
    }
}

// ---------------------------------------------------------------------------
// Kernel 2: scan, 1024 threads (32 warps), 4 groups of 128 per batch row.
// Group g computes the word-g partial of every dot (short chains); the owner
// group (g==0) combines partials ((p0+p1)+p2)+p3 — the R6-proven-bit-stable
// split-K association — and runs the elementwise updates (R8 numerics).
// 4 barriers per step.
// ---------------------------------------------------------------------------
#define SCAN_SMEM_FLOATS (3 * 16384 + 3 * 128 + 3 * 1024 + 24 + 192)

__global__ __launch_bounds__(1024) void scan_kernel(
    const float* __restrict__ mask,
    const float* __restrict__ w_h1h1, const float* __restrict__ b_h1h1,
    const float* __restrict__ w_h1h2, const float* __restrict__ b_h1h2,
    const float* __restrict__ w_h2h2, const float* __restrict__ b_h2h2,
    const float* __restrict__ tau_adp_h1, const float* __restrict__ tau_adp_h2,
    const float* __restrict__ tau_m_h1,   const float* __restrict__ tau_m_h2,
    const float* __restrict__ hid1_mem0, const float* __restrict__ hid2_mem0,
    float* __restrict__ out)
{
    extern __shared__ float sm[];
    float*  w11  = sm;
    float*  w12  = w11 + 16384;
    float*  w22  = w12 + 16384;
    float*  b11s = w22 + 16384;
    float*  b12s = b11s + 128;
    float*  b22s = b12s + 128;
    float*  part1 = b22s + 128;               // [2 row][4 word][128 h]
    float*  part2 = part1 + 1024;             // [2 row][4 word][128 h]
    float*  part3 = part2 + 1024;             // [2 row][4 word][128 h]
    int*      cntU1 = (int*)(part3 + 1024);   // [2 par][2 row][4 word]
    int*      cnt2  = cntU1 + 16;             // [2 row][4 word]
    uint8_t*  lstU1 = (uint8_t*)(cnt2 + 8);   // [2 par][2 row][4 word][32]
    uint8_t*  lst2  = lstU1 + 512;            // [2 row][4 word][32]

    const int tid = threadIdx.x;
    const int h   = tid & 127;
    const int g   = (tid >> 7) & 3;    // group (word) 0..3
    const int r   = tid >> 9;          // batch row within pair
    const int l   = tid & 31;
    const int myw = (tid >> 5) & 3;    // warp index within group
    const int b   = blockIdx.x * 2 + r;

#pragma unroll 4
    for (int p_ = 0; p_ < 16; p_++) {
        int i = p_ * 1024 + tid;
        w11[i] = __fmul_rn(w_h1h1[i], mask[i]);
        w12[i] = w_h1h2[i];
        w22[i] = __fmul_rn(w_h2h2[i], mask[16384 + i]);
    }
    if (tid < 128) {
        b11s[tid] = b_h1h1[tid];
        b12s[tid] = b_h1h2[tid];
        b22s[tid] = b_h2h2[tid];
    }
    if (tid < 24) cntU1[tid] = 0;

    // Owner-group state (only meaningful for g==0 threads)
    float a1 = 0.f, r1 = 0.f, a2 = 0.f, r2 = 0.f;
    float oma1 = 0.f, omr1 = 0.f, oma2 = 0.f, omr2 = 0.f;
    float h1m = 0.f, h2m = 0.f;
    if (g == 0) {
        a1 = exp_cr(__fdiv_rn(-1.0f, tau_m_h1[h]));
        r1 = exp_cr(__fdiv_rn(-1.0f, tau_adp_h1[h]));
        a2 = exp_cr(__fdiv_rn(-1.0f, tau_m_h2[h]));
        r2 = exp_cr(__fdiv_rn(-1.0f, tau_adp_h2[h]));
        oma1 = __fsub_rn(1.f, a1);
        omr1 = __fsub_rn(1.f, r1);
        oma2 = __fsub_rn(1.f, a2);
        omr2 = __fsub_rn(1.f, r2);
        h1m = hid1_mem0[(size_t)b * 128 + h];
        h2m = hid2_mem0[(size_t)b * 128 + h];
    }
    float h1sp = 0.f, h2sp = 0.f;
    float bb1 = 0.01f, bb2 = 0.01f;
    float cnt1c = 0.f, cnt2c = 0.f;

    __syncthreads();

    const float* xin  = g_xin + (size_t)b * TT * HH + h;
    const float* w11h = w11 + h;
    const float* w12h = w12 + h;
    const float* w22h = w22 + h;
    const int r4 = (r << 2);
    const int pb = r4 * 128 + h;       // base into part arrays for word 0
    float xa = (g == 0) ? xin[0] : 0.f;
    int p = 0;

    for (int t = 0; t < TT; t++) {
        // ---- Phase 1: group g computes dot1 word-g and dot2 word-g ----
        float p1 = 0.f, p2 = 0.f;
        {
            const int slot1 = ((p * 2 + r) << 2) + g;
            int c = cntU1[slot1];
            const uint8_t* lp = lstU1 + (slot1 << 5);
#pragma unroll 4
            for (int i = 0; i < c; i++)
                p1 = __fadd_rn(p1, w11h[(int)lp[i] << 7]);
            const int slot2 = r4 + g;
            c = cnt2[slot2];
            lp = lst2 + (slot2 << 5);
#pragma unroll 4
            for (int i = 0; i < c; i++)
                p2 = __fadd_rn(p2, w22h[(int)lp[i] << 7]);
        }
        if (g) {
            part1[pb + (g << 7)] = p1;
            part2[pb + (g << 7)] = p2;
        }
        __syncthreads();   // A

        // ---- Phase 2: owner combines dot1, update1, publish s1 lists ----
        if (g == 0) {
            float m1 = __fadd_rn(__fadd_rn(__fadd_rn(p1, part1[pb + 128]),
                                           part1[pb + 256]), part1[pb + 384]);
            float i1 = __fadd_rn(__fadd_rn(xa, m1), b11s[h]);
            bb1 = __fadd_rn(__fmul_rn(r1, bb1), __fmul_rn(omr1, h1sp));
            float B1 = __fadd_rn(0.01f, __fmul_rn(1.8f, bb1));
            h1m = __fsub_rn(__fadd_rn(__fmul_rn(h1m, a1), __fmul_rn(oma1, i1)),
                            __fmul_rn(B1, h1sp));
            float s1n = (__fsub_rn(h1m, B1) > 0.f) ? 1.f : 0.f;
            cnt1c += s1n; h1sp = s1n;

            unsigned int wd1 = __ballot_sync(0xffffffffu, s1n != 0.f);
            const int slot = (((p ^ 1) * 2 + r) << 2) + myw;
            if ((wd1 >> l) & 1u) {
                int pos = __popc(wd1 & ((1u << l) - 1u));
                lstU1[(slot << 5) + pos] = (uint8_t)((myw << 5) | l);
            }
            if (l == 0) cntU1[slot] = __popc(wd1);
            // prefetch next xin while helpers idle
            xa = (t + 1 < TT) ? xin[(size_t)(t + 1) * HH] : 0.f;
        }
        __syncthreads();   // B

        // ---- Phase 3: group g computes dot3 word-g over NEW s1 ----
        float p3 = 0.f;
        {
            const int slot = (((p ^ 1) * 2 + r) << 2) + g;
            int c = cntU1[slot];
            const uint8_t* lp = lstU1 + (slot << 5);
#pragma unroll 4
            for (int i = 0; i < c; i++)
                p3 = __fadd_rn(p3, w12h[(int)lp[i] << 7]);
        }
        if (g) part3[pb + (g << 7)] = p3;
        __syncthreads();   // C

        // ---- Phase 4: owner combines dot3+dot2, update2, publish s2 ----
        if (g == 0) {
            float m12 = __fadd_rn(__fadd_rn(__fadd_rn(p3, part3[pb + 128]),
                                            part3[pb + 256]), part3[pb + 384]);
            float m22 = __fadd_rn(__fadd_rn(__fadd_rn(p2, part2[pb + 128]),
                                            part2[pb + 256]), part2[pb + 384]);
            float i2 = __fadd_rn(__fadd_rn(__fadd_rn(m12, b12s[h]), m22), b22s[h]);
            bb2 = __fadd_rn(__fmul_rn(r2, bb2), __fmul_rn(omr2, h2sp));
            float B2 = __fadd_rn(0.01f, __fmul_rn(1.8f, bb2));
            h2m = __fsub_rn(__fadd_rn(__fmul_rn(h2m, a2), __fmul_rn(oma2, i2)),
                            __fmul_rn(B2, h2sp));
            float s2n = (__fsub_rn(h2m, B2) > 0.f) ? 1.f : 0.f;
            cnt2c += s2n; h2sp = s2n;

            unsigned int wd2 = __ballot_sync(0xffffffffu, s2n != 0.f);
            const int slot = r4 + myw;
            if ((wd2 >> l) & 1u) {
                int pos = __popc(wd2 & ((1u << l) - 1u));
                lst2[(slot << 5) + pos] = (uint8_t)((myw << 5) | l);
            }
            if (l == 0) {
                cnt2[slot] = __popc(wd2);
                g_spk[((size_t)b * TT + t) * 4 + myw] = wd2;
            }
        }
        __syncthreads();   // D

        p ^= 1;
    }

    if (g == 0) {
        const float T250 = 250.0f;
        out[5120 + (size_t)b * 128 + h]         = cnt1c / T250;
        out[5120 + 32768 + (size_t)b * 128 + h] = cnt2c / T250;
    }
}

// ---------------------------------------------------------------------------
// Kernel 3: readout — unchanged from R14/R15 (43us, passing).
// ---------------------------------------------------------------------------
__global__ __launch_bounds__(128) void readout_kernel(
    const float* __restrict__ w_h2o, const float* __restrict__ b_h2o,
    const float* __restrict__ tau_m_o, const float* __restrict__ out_mem0,
    float* __restrict__ out)
{
    __shared__ float w2o_sm[128 * 20];
    __shared__ unsigned int spk[TT][4];
    __shared__ float om_sm[TT][20];
    __shared__ float red[128][20];

    const int b = blockIdx.x;
    const int tid = threadIdx.x;

    for (int i = tid; i < 128 * 20; i += 128) w2o_sm[i] = w_h2o[i];
    for (int i = tid; i < TT * 4; i += 128)
        ((unsigned int*)spk)[i] = g_spk[(size_t)b * TT * 4 + i];
    __syncthreads();

    for (int pidx = tid; pidx < TT * 20; pidx += 128) {
        int t = pidx / 20;
        int o = pidx - t * 20;
        float acc = 0.f;
#pragma unroll
        for (int w = 0; w < 4; w++) {
            unsigned int word = spk[t][w];
            while (word) {
                int j = __ffs(word) - 1; word &= word - 1;
                acc = __fadd_rn(acc, w2o_sm[(w * 32 + j) * 20 + o]);
            }
        }
        om_sm[t][o] = acc;
    }
    __syncthreads();

    if (tid < 32) {
        const int ll = tid;
        float om = 0.f, ao = 0.f, bo = 0.f;
        if (ll < 20) {
            om = out_mem0[(size_t)b * 20 + ll];
            ao = exp_cr(__fdiv_rn(-1.0f, tau_m_o[ll]));
            bo = b_h2o[ll];
        }
        const float omao = __fsub_rn(1.f, ao);
        for (int t = 0; t < TT; t++) {
            float iov = (ll < 20) ? __fadd_rn(om_sm[t][ll], bo) : 0.f;
            om = __fadd_rn(__fmul_rn(om, ao), __fmul_rn(omao, iov));
            if (ll < 20) om_sm[t][ll] = om;
        }
    }
    __syncthreads();

    float acc[20];
#pragma unroll
    for (int o = 0; o < 20; o++) acc[o] = 0.f;

    for (int t = 11 + tid; t < TT; t += 128) {
        float omv[20];
#pragma unroll
        for (int o = 0; o < 20; o++) omv[o] = om_sm[t][o];
        float v = omv[0];
#pragma unroll
        for (int o = 1; o < 20; o++) v = fmaxf(v, omv[o]);
        float e[20];
#pragma unroll
        for (int o = 0; o < 20; o++) e[o] = expf(__fsub_rn(omv[o], v));
        float ssum = 0.f;
#pragma unroll
        for (int o = 0; o < 20; o++) ssum = __fadd_rn(ssum, e[o]);
#pragma unroll
        for (int o = 0; o < 20; o++)
            acc[o] = __fadd_rn(acc[o], __fdiv_rn(e[o], ssum));
    }

#pragma unroll
    for (int o = 0; o < 20; o++) red[tid][o] = acc[o];
    __syncthreads();
#pragma unroll
    for (int s = 64; s > 0; s >>= 1) {
        if (tid < s) {
#pragma unroll
            for (int o = 0; o < 20; o++)
                red[tid][o] = __fadd_rn(red[tid][o], red[tid + s][o]);
        }
        __syncthreads();
    }
    if (tid < 20) out[(size_t)b * 20 + tid] = red[0][tid];
}

// ---------------------------------------------------------------------------
// Kernel 4: A_norm — unchanged. Launched first.
// ---------------------------------------------------------------------------
__global__ __launch_bounds__(256) void anorm_kernel(
    const float* __restrict__ w_h1h1, const float* __restrict__ w_h2h2,
    const float* __restrict__ mask, float* __restrict__ out)
{
    __shared__ float red1[256];
    __shared__ float red2[256];
    int tid = threadIdx.x;
    float s1 = 0.f, s2 = 0.f;
    for (int i = tid; i < 16384; i += 256) {
        s1 = __fadd_rn(s1, fabsf(__fmul_rn(w_h1h1[i], mask[i])));
        s2 = __fadd_rn(s2, fabsf(__fmul_rn(w_h2h2[i], mask[16384 + i])));
    }
    red1[tid] = s1;
    red2[tid] = s2;
    __syncthreads();
#pragma unroll
    for (int st = 128; st > 0; st >>= 1) {
        if (tid < st) {
            red1[tid] = __fadd_rn(red1[tid], red1[tid + st]);
            red2[tid] = __fadd_rn(red2[tid], red2[tid + st]);
        }
        __syncthreads();
    }
    if (tid == 0) out[5120 + 2 * 32768] = __fadd_rn(red1[0], red2[0]);
}

// Marker no-op: keeps the fixed ncu capture window on the scan.
__global__ void marker_kernel() {}

// ---------------------------------------------------------------------------
extern "C" void kernel_launch(void* const* d_in, const int* in_sizes, int n_in,
                              void* d_out, int out_size)
{
    (void)in_sizes; (void)n_in; (void)out_size;
    const float* x          = (const float*)d_in[0];
    const float* mask       = (const float*)d_in[1];
    const float* w_ih1      = (const float*)d_in[2];
    const float* b_ih1      = (const float*)d_in[3];
    const float* w_h1h1     = (const float*)d_in[4];
    const float* b_h1h1     = (const float*)d_in[5];
    const float* w_h1h2     = (const float*)d_in[6];
    const float* b_h1h2     = (const float*)d_in[7];
    const float* w_h2h2     = (const float*)d_in[8];
    const float* b_h2h2     = (const float*)d_in[9];
    const float* w_h2o      = (const float*)d_in[10];
    const float* b_h2o      = (const float*)d_in[11];
    const float* tau_adp_h1 = (const float*)d_in[12];
    const float* tau_adp_h2 = (const float*)d_in[13];
    const float* tau_m_h1   = (const float*)d_in[14];
    const float* tau_m_h2   = (const float*)d_in[15];
    const float* tau_m_o    = (const float*)d_in[16];
    const float* hid1_mem0  = (const float*)d_in[17];
    const float* hid2_mem0  = (const float*)d_in[18];
    const float* out_mem0   = (const float*)d_in[19];
    float* out = (float*)d_out;

    anorm_kernel<<<1, 256>>>(w_h1h1, w_h2h2, mask, out);

    gemm_xin_kernel<<<(BT * TT) / 128, 256>>>(x, w_ih1, b_ih1);

    marker_kernel<<<1, 32>>>();

    const int smem_bytes = SCAN_SMEM_FLOATS * (int)sizeof(float);
    cudaFuncSetAttribute(scan_kernel, cudaFuncAttributeMaxDynamicSharedMemorySize,
                         smem_bytes);
    scan_kernel<<<BT / 2, 1024, smem_bytes>>>(
        mask, w_h1h1, b_h1h1, w_h1h2, b_h1h2, w_h2h2, b_h2h2,
        tau_adp_h1, tau_adp_h2, tau_m_h1, tau_m_h2,
        hid1_mem0, hid2_mem0, out);

    readout_kernel<<<BT, 128>>>(w_h2o, b_h2o, tau_m_o, out_mem0, out);
}

// round 17
// speedup vs baseline: 1.8659x; 1.0672x over previous
#include <cuda_runtime.h>
#include <cstdint>
#include <cstddef>

#define BT 256
#define TT 250
#define II 700
#define HH 128
#define OO 20

// Scratch: xin[b][t][h] = (x @ w_ih1 + b_ih1)
__device__ float g_xin[BT * TT * HH];
// layer-2 spike bit-words: [b][t][4]
__device__ unsigned int g_spk[BT * TT * 4];

// Correctly-rounded f32 exp (matches glibc scalar expf used by XLA:CPU).
__device__ __forceinline__ float exp_cr(float x) {
    return (float)exp((double)x);
}

// packed f32x2 helpers
__device__ __forceinline__ unsigned long long pack2(float lo, float hi) {
    unsigned long long r;
    asm("mov.b64 %0, {%1, %2};" : "=l"(r) : "f"(lo), "f"(hi));
    return r;
}
__device__ __forceinline__ void unpack2(unsigned long long v, float& lo, float& hi) {
    asm("mov.b64 {%0, %1}, %2;" : "=f"(lo), "=f"(hi) : "l"(v));
}
__device__ __forceinline__ void ffma2(unsigned long long& d, unsigned long long a,
                                      unsigned long long b) {
    asm("fma.rn.f32x2 %0, %1, %2, %0;" : "+l"(d) : "l"(a), "l"(b));
}

// ---------------------------------------------------------------------------
// Kernel 1: xin GEMM. BM=64 (grid 1000) for finer wave balance + higher
// occupancy; per-output ascending-k FMA chain UNCHANGED -> bit-identical xin.
// ---------------------------------------------------------------------------
__global__ __launch_bounds__(256) void gemm_xin_kernel(
    const float* __restrict__ x, const float* __restrict__ w,
    const float* __restrict__ bias)
{
    __shared__ float a_sm[16][68];    // [k][m] transposed, padded
    __shared__ float b_sm[16][128];

    const int tid = threadIdx.x;
    const int m0 = blockIdx.x * 64;
    const int tx = tid & 15, ty = tid >> 4;
    const int r0 = ty * 4;

    const int a_ml = tid >> 4, a_kl = tid & 15;   // + p*16 rows, p<4
    const int b_kl = tid >> 7, b_hh = tid & 127;  // + p*2 rows, p<8

    unsigned long long acc[4][4];
#pragma unroll
    for (int r = 0; r < 4; r++)
#pragma unroll
        for (int j = 0; j < 4; j++) acc[r][j] = 0ull;

    const int NT = (II + 15) / 16;
    float ra[4], rb[8];

    {
        int k0 = 0;
#pragma unroll
        for (int p = 0; p < 4; p++) {
            int k = k0 + a_kl;
            ra[p] = (k < II) ? x[(size_t)(m0 + a_ml + p * 16) * II + k] : 0.f;
        }
#pragma unroll
        for (int p = 0; p < 8; p++) {
            int k = k0 + b_kl + p * 2;
            rb[p] = (k < II) ? w[k * HH + b_hh] : 0.f;
        }
    }

    for (int kt = 0; kt < NT; kt++) {
#pragma unroll
        for (int p = 0; p < 4; p++) a_sm[a_kl][a_ml + p * 16] = ra[p];
#pragma unroll
        for (int p = 0; p < 8; p++) b_sm[b_kl + p * 2][b_hh] = rb[p];
        __syncthreads();

        if (kt + 1 < NT) {
            int k0 = (kt + 1) * 16;
#pragma unroll
            for (int p = 0; p < 4; p++) {
                int k = k0 + a_kl;
                ra[p] = (k < II) ? x[(size_t)(m0 + a_ml + p * 16) * II + k] : 0.f;
            }
#pragma unroll
            for (int p = 0; p < 8; p++) {
                int k = k0 + b_kl + p * 2;
                rb[p] = (k < II) ? w[k * HH + b_hh] : 0.f;
            }
        }

#pragma unroll
        for (int kk = 0; kk < 16; kk++) {
            float a[4];
            unsigned long long bb[4];
#pragma unroll
            for (int r = 0; r < 4; r++) a[r] = a_sm[kk][r0 + r];
            const float2* bp = reinterpret_cast<const float2*>(&b_sm[kk][2 * tx]);
#pragma unroll
            for (int j = 0; j < 4; j++) { float2 v = bp[16 * j]; bb[j] = pack2(v.x, v.y); }
#pragma unroll
            for (int r = 0; r < 4; r++) {
                unsigned long long ad = pack2(a[r], a[r]);
#pragma unroll
                for (int j = 0; j < 4; j++) ffma2(acc[r][j], ad, bb[j]);
            }
        }
        __syncthreads();
    }

#pragma unroll
    for (int r = 0; r < 4; r++) {
        int m = m0 + r0 + r;
#pragma unroll
        for (int j = 0; j < 4; j++) {
            float lo, hi;
            unpack2(acc[r][j], lo, hi);
            int c = 2 * tx + 32 * j;
            float2 v;
            v.x = __fadd_rn(lo, bias[c]);
            v.y = __fadd_rn(hi, bias[c + 1]);
            *reinterpret_cast<float2*>(&g_xin[(size_t)m * HH + c]) = v;
        }
    }
}

// ---------------------------------------------------------------------------
// Kernel 2: scan, 1024 threads, 3-phase step:
//   P_A (owner): combine dot1 partials -> update1 -> publish s1 lists
//   P_B (all):   dot3(t), dot1(t+1) [same s1 list, 2 accumulators],
//                dot2(t) [s2(t-1) list] — word-g partials
//   P_C (owner): combine dot3/dot2 -> update2 -> publish s2 lists
// 3 barriers/step. All chain/combine orders identical to R16 -> bit-identical.
// ---------------------------------------------------------------------------
#define SCAN_SMEM_FLOATS (3 * 16384 + 3 * 128 + 3 * 1024 + 160)

__global__ __launch_bounds__(1024) void scan_kernel(
    const float* __restrict__ mask,
    const float* __restrict__ w_h1h1, const float* __restrict__ b_h1h1,
    const float* __restrict__ w_h1h2, const float* __restrict__ b_h1h2,
    const float* __restrict__ w_h2h2, const float* __restrict__ b_h2h2,
    const float* __restrict__ tau_adp_h1, const float* __restrict__ tau_adp_h2,
    const float* __restrict__ tau_m_h1,   const float* __restrict__ tau_m_h2,
    const float* __restrict__ hid1_mem0, const float* __restrict__ hid2_mem0,
    float* __restrict__ out)
{
    extern __shared__ float sm[];
    float*  w11  = sm;
    float*  w12  = w11 + 16384;
    float*  w22  = w12 + 16384;
    float*  b11s = w22 + 16384;
    float*  b12s = b11s + 128;
    float*  b22s = b12s + 128;
    float*  part1 = b22s + 128;               // [2 row][4 word][128 h]
    float*  part2 = part1 + 1024;
    float*  part3 = part2 + 1024;
    int*      cnt1  = (int*)(part3 + 1024);   // [2 row][4 word]
    int*      cnt2s = cnt1 + 8;               // [2 row][4 word]
    uint8_t*  lst1  = (uint8_t*)(cnt2s + 8);  // [2 row][4 word][32]
    uint8_t*  lst2  = lst1 + 256;             // [2 row][4 word][32]

    const int tid = threadIdx.x;
    const int h   = tid & 127;
    const int g   = (tid >> 7) & 3;    // group (word) 0..3
    const int r   = tid >> 9;          // batch row within pair
    const int l   = tid & 31;
    const int myw = (tid >> 5) & 3;    // warp index within group
    const int b   = blockIdx.x * 2 + r;

#pragma unroll 4
    for (int p_ = 0; p_ < 16; p_++) {
        int i = p_ * 1024 + tid;
        w11[i] = __fmul_rn(w_h1h1[i], mask[i]);
        w12[i] = w_h1h2[i];
        w22[i] = __fmul_rn(w_h2h2[i], mask[16384 + i]);
    }
    if (tid < 128) {
        b11s[tid] = b_h1h1[tid];
        b12s[tid] = b_h1h2[tid];
        b22s[tid] = b_h2h2[tid];
    }
    if (tid < 16) cnt1[tid] = 0;       // covers cnt1[0..7] + cnt2s[0..7]
    for (int i = tid; i < 3072; i += 1024) part1[i] = 0.f;  // part1..part3

    // Owner-group state
    float a1 = 0.f, r1 = 0.f, a2 = 0.f, r2 = 0.f;
    float oma1 = 0.f, omr1 = 0.f, oma2 = 0.f, omr2 = 0.f;
    float h1m = 0.f, h2m = 0.f;
    if (g == 0) {
        a1 = exp_cr(__fdiv_rn(-1.0f, tau_m_h1[h]));
        r1 = exp_cr(__fdiv_rn(-1.0f, tau_adp_h1[h]));
        a2 = exp_cr(__fdiv_rn(-1.0f, tau_m_h2[h]));
        r2 = exp_cr(__fdiv_rn(-1.0f, tau_adp_h2[h]));
        oma1 = __fsub_rn(1.f, a1);
        omr1 = __fsub_rn(1.f, r1);
        oma2 = __fsub_rn(1.f, a2);
        omr2 = __fsub_rn(1.f, r2);
        h1m = hid1_mem0[(size_t)b * 128 + h];
        h2m = hid2_mem0[(size_t)b * 128 + h];
    }
    float h1sp = 0.f, h2sp = 0.f;
    float bb1 = 0.01f, bb2 = 0.01f;
    float cnt1c = 0.f, cnt2c = 0.f;

    __syncthreads();

    const float* xin  = g_xin + (size_t)b * TT * HH + h;
    const float* w11h = w11 + h;
    const float* w12h = w12 + h;
    const float* w22h = w22 + h;
    const int pb   = (r << 9) + h;     // part base for word 0
    const int slot = (r << 2) + g;     // this group's list slot
    float xa = (g == 0) ? xin[0] : 0.f;

    // owner-held partials across phases
    float p1cur = 0.f;   // dot1(t) word-0 partial (from previous P_B)
    float p2own = 0.f, p3own = 0.f;

    for (int t = 0; t < TT; t++) {
        // ---- P_A: owner combines dot1, update1, publish s1 lists ----
        if (g == 0) {
            float m1 = __fadd_rn(__fadd_rn(__fadd_rn(p1cur, part1[pb + 128]),
                                           part1[pb + 256]), part1[pb + 384]);
            float i1 = __fadd_rn(__fadd_rn(xa, m1), b11s[h]);
            bb1 = __fadd_rn(__fmul_rn(r1, bb1), __fmul_rn(omr1, h1sp));
            float B1 = __fadd_rn(0.01f, __fmul_rn(1.8f, bb1));
            h1m = __fsub_rn(__fadd_rn(__fmul_rn(h1m, a1), __fmul_rn(oma1, i1)),
                            __fmul_rn(B1, h1sp));
            float s1n = (__fsub_rn(h1m, B1) > 0.f) ? 1.f : 0.f;
            cnt1c += s1n; h1sp = s1n;

            unsigned int wd1 = __ballot_sync(0xffffffffu, s1n != 0.f);
            const int s1slot = (r << 2) + myw;
            if ((wd1 >> l) & 1u) {
                int pos = __popc(wd1 & ((1u << l) - 1u));
                lst1[(s1slot << 5) + pos] = (uint8_t)((myw << 5) | l);
            }
            if (l == 0) cnt1[s1slot] = __popc(wd1);
            xa = (t + 1 < TT) ? xin[(size_t)(t + 1) * HH] : 0.f;
        }
        __syncthreads();   // bar1: s1 lists visible

        // ---- P_B: all groups — dot3(t) + dot1(t+1) (shared s1 list) and
        //      dot2(t) (s2(t-1) list), word-g partials ----
        {
            float p3 = 0.f, p1n = 0.f, p2 = 0.f;
            int c = cnt1[slot];
            const uint8_t* lp = lst1 + (slot << 5);
#pragma unroll 4
            for (int i = 0; i < c; i++) {
                int off = (int)lp[i] << 7;
                p3  = __fadd_rn(p3,  w12h[off]);
                p1n = __fadd_rn(p1n, w11h[off]);
            }
            c = cnt2s[slot];
            lp = lst2 + (slot << 5);
#pragma unroll 4
            for (int i = 0; i < c; i++)
                p2 = __fadd_rn(p2, w22h[(int)lp[i] << 7]);

            if (g) {
                part3[pb + (g << 7)] = p3;
                part1[pb + (g << 7)] = p1n;
                part2[pb + (g << 7)] = p2;
            } else {
                p3own = p3; p1cur = p1n; p2own = p2;
            }
        }
        __syncthreads();   // bar2: partials visible

        // ---- P_C: owner combines dot3/dot2, update2, publish s2 lists ----
        if (g == 0) {
            float m12 = __fadd_rn(__fadd_rn(__fadd_rn(p3own, part3[pb + 128]),
                                            part3[pb + 256]), part3[pb + 384]);
            float m22 = __fadd_rn(__fadd_rn(__fadd_rn(p2own, part2[pb + 128]),
                                            part2[pb + 256]), part2[pb + 384]);
            float i2 = __fadd_rn(__fadd_rn(__fadd_rn(m12, b12s[h]), m22), b22s[h]);
            bb2 = __fadd_rn(__fmul_rn(r2, bb2), __fmul_rn(omr2, h2sp));
            float B2 = __fadd_rn(0.01f, __fmul_rn(1.8f, bb2));
            h2m = __fsub_rn(__fadd_rn(__fmul_rn(h2m, a2), __fmul_rn(oma2, i2)),
                            __fmul_rn(B2, h2sp));
            float s2n = (__fsub_rn(h2m, B2) > 0.f) ? 1.f : 0.f;
            cnt2c += s2n; h2sp = s2n;

            unsigned int wd2 = __ballot_sync(0xffffffffu, s2n != 0.f);
            const int s2slot = (r << 2) + myw;
            if ((wd2 >> l) & 1u) {
                int pos = __popc(wd2 & ((1u << l) - 1u));
                lst2[(s2slot << 5) + pos] = (uint8_t)((myw << 5) | l);
            }
            if (l == 0) {
                cnt2s[s2slot] = __popc(wd2);
                g_spk[((size_t)b * TT + t) * 4 + myw] = wd2;
            }
        }
        __syncthreads();   // bar3: s2 lists visible for next P_B
    }

    if (g == 0) {
        const float T250 = 250.0f;
        out[5120 + (size_t)b * 128 + h]         = cnt1c / T250;
        out[5120 + 32768 + (size_t)b * 128 + h] = cnt2c / T250;
    }
}

// ---------------------------------------------------------------------------
// Kernel 3: readout — unchanged (43us, passing).
// ---------------------------------------------------------------------------
__global__ __launch_bounds__(128) void readout_kernel(
    const float* __restrict__ w_h2o, const float* __restrict__ b_h2o,
    const float* __restrict__ tau_m_o, const float* __restrict__ out_mem0,
    float* __restrict__ out)
{
    __shared__ float w2o_sm[128 * 20];
    __shared__ unsigned int spk[TT][4];
    __shared__ float om_sm[TT][20];
    __shared__ float red[128][20];

    const int b = blockIdx.x;
    const int tid = threadIdx.x;

    for (int i = tid; i < 128 * 20; i += 128) w2o_sm[i] = w_h2o[i];
    for (int i = tid; i < TT * 4; i += 128)
        ((unsigned int*)spk)[i] = g_spk[(size_t)b * TT * 4 + i];
    __syncthreads();

    for (int pidx = tid; pidx < TT * 20; pidx += 128) {
        int t = pidx / 20;
        int o = pidx - t * 20;
        float acc = 0.f;
#pragma unroll
        for (int w = 0; w < 4; w++) {
            unsigned int word = spk[t][w];
            while (word) {
                int j = __ffs(word) - 1; word &= word - 1;
                acc = __fadd_rn(acc, w2o_sm[(w * 32 + j) * 20 + o]);
            }
        }
        om_sm[t][o] = acc;
    }
    __syncthreads();

    if (tid < 32) {
        const int ll = tid;
        float om = 0.f, ao = 0.f, bo = 0.f;
        if (ll < 20) {
            om = out_mem0[(size_t)b * 20 + ll];
            ao = exp_cr(__fdiv_rn(-1.0f, tau_m_o[ll]));
            bo = b_h2o[ll];
        }
        const float omao = __fsub_rn(1.f, ao);
        for (int t = 0; t < TT; t++) {
            float iov = (ll < 20) ? __fadd_rn(om_sm[t][ll], bo) : 0.f;
            om = __fadd_rn(__fmul_rn(om, ao), __fmul_rn(omao, iov));
            if (ll < 20) om_sm[t][ll] = om;
        }
    }
    __syncthreads();

    float acc[20];
#pragma unroll
    for (int o = 0; o < 20; o++) acc[o] = 0.f;

    for (int t = 11 + tid; t < TT; t += 128) {
        float omv[20];
#pragma unroll
        for (int o = 0; o < 20; o++) omv[o] = om_sm[t][o];
        float v = omv[0];
#pragma unroll
        for (int o = 1; o < 20; o++) v = fmaxf(v, omv[o]);
        float e[20];
#pragma unroll
        for (int o = 0; o < 20; o++) e[o] = expf(__fsub_rn(omv[o], v));
        float ssum = 0.f;
#pragma unroll
        for (int o = 0; o < 20; o++) ssum = __fadd_rn(ssum, e[o]);
#pragma unroll
        for (int o = 0; o < 20; o++)
            acc[o] = __fadd_rn(acc[o], __fdiv_rn(e[o], ssum));
    }

#pragma unroll
    for (int o = 0; o < 20; o++) red[tid][o] = acc[o];
    __syncthreads();
#pragma unroll
    for (int s = 64; s > 0; s >>= 1) {
        if (tid < s) {
#pragma unroll
            for (int o = 0; o < 20; o++)
                red[tid][o] = __fadd_rn(red[tid][o], red[tid + s][o]);
        }
        __syncthreads();
    }
    if (tid < 20) out[(size_t)b * 20 + tid] = red[0][tid];
}

// ---------------------------------------------------------------------------
// Kernel 4: A_norm — unchanged. Launched first.
// ---------------------------------------------------------------------------
__global__ __launch_bounds__(256) void anorm_kernel(
    const float* __restrict__ w_h1h1, const float* __restrict__ w_h2h2,
    const float* __restrict__ mask, float* __restrict__ out)
{
    __shared__ float red1[256];
    __shared__ float red2[256];
    int tid = threadIdx.x;
    float s1 = 0.f, s2 = 0.f;
    for (int i = tid; i < 16384; i += 256) {
        s1 = __fadd_rn(s1, fabsf(__fmul_rn(w_h1h1[i], mask[i])));
        s2 = __fadd_rn(s2, fabsf(__fmul_rn(w_h2h2[i], mask[16384 + i])));
    }
    red1[tid] = s1;
    red2[tid] = s2;
    __syncthreads();
#pragma unroll
    for (int st = 128; st > 0; st >>= 1) {
        if (tid < st) {
            red1[tid] = __fadd_rn(red1[tid], red1[tid + st]);
            red2[tid] = __fadd_rn(red2[tid], red2[tid + st]);
        }
        __syncthreads();
    }
    if (tid == 0) out[5120 + 2 * 32768] = __fadd_rn(red1[0], red2[0]);
}

// Marker no-op: keeps the fixed ncu capture window on the scan.
__global__ void marker_kernel() {}

// ---------------------------------------------------------------------------
extern "C" void kernel_launch(void* const* d_in, const int* in_sizes, int n_in,
                              void* d_out, int out_size)
{
    (void)in_sizes; (void)n_in; (void)out_size;
    const float* x          = (const float*)d_in[0];
    const float* mask       = (const float*)d_in[1];
    const float* w_ih1      = (const float*)d_in[2];
    const float* b_ih1      = (const float*)d_in[3];
    const float* w_h1h1     = (const float*)d_in[4];
    const float* b_h1h1     = (const float*)d_in[5];
    const float* w_h1h2     = (const float*)d_in[6];
    const float* b_h1h2     = (const float*)d_in[7];
    const float* w_h2h2     = (const float*)d_in[8];
    const float* b_h2h2     = (const float*)d_in[9];
    const float* w_h2o      = (const float*)d_in[10];
    const float* b_h2o      = (const float*)d_in[11];
    const float* tau_adp_h1 = (const float*)d_in[12];
    const float* tau_adp_h2 = (const float*)d_in[13];
    const float* tau_m_h1   = (const float*)d_in[14];
    const float* tau_m_h2   = (const float*)d_in[15];
    const float* tau_m_o    = (const float*)d_in[16];
    const float* hid1_mem0  = (const float*)d_in[17];
    const float* hid2_mem0  = (const float*)d_in[18];
    const float* out_mem0   = (const float*)d_in[19];
    float* out = (float*)d_out;

    anorm_kernel<<<1, 256>>>(w_h1h1, w_h2h2, mask, out);

    gemm_xin_kernel<<<(BT * TT) / 64, 256>>>(x, w_ih1, b_ih1);

    marker_kernel<<<1, 32>>>();

    const int smem_bytes = SCAN_SMEM_FLOATS * (int)sizeof(float);
    cudaFuncSetAttribute(scan_kernel, cudaFuncAttributeMaxDynamicSharedMemorySize,
                         smem_bytes);
    scan_kernel<<<BT / 2, 1024, smem_bytes>>>(
        mask, w_h1h1, b_h1h1, w_h1h2, b_h1h2, w_h2h2, b_h2h2,
        tau_adp_h1, tau_adp_h2, tau_m_h1, tau_m_h2,
        hid1_mem0, hid2_mem0, out);

    readout_kernel<<<BT, 128>>>(w_h2o, b_h2o, tau_m_o, out_mem0, out);
}